// round 6
// baseline (speedup 1.0000x reference)
#include <cuda_runtime.h>
#include <cuda_bf16.h>
#include <math.h>
#include <stdint.h>

// ---------------- problem constants ----------------
#define BATCH    2
#define SEQLEN   1024
#define DMODEL   1024
#define DINNER   2048
#define NHEADS   32
#define HEADDIM  64
#define DSTATE   128
#define DCONV    4
#define CONVDIM  2304          // DINNER + 2*DSTATE
#define DINPROJ  4384          // 2*DINNER + 2*DSTATE + NHEADS
#define ROWS     (BATCH*SEQLEN)   // 2048
#define EPS      1e-5f
#define NCHUNK   4
#define CLEN     (SEQLEN/NCHUNK)  // 256

// ---------------- scratch (static device allocations only) ----------------
__device__ __align__(1024) float g_zx [ROWS*DINPROJ];
__device__ __align__(1024) float g_xbc[ROWS*CONVDIM];
__device__ __align__(1024) float g_dt [ROWS*NHEADS];
__device__ __align__(1024) float g_dA [ROWS*NHEADS];
__device__ __align__(1024) float g_cum[ROWS*NHEADS];          // within-chunk cumprod of dA
__device__ __align__(1024) float g_yp0[ROWS*DINNER];
__device__ __align__(1024) float g_yp1[ROWS*DINNER];
__device__ __align__(1024) float g_yp2[ROWS*DINNER];
__device__ __align__(1024) float g_yp3[ROWS*DINNER];
// chunk end-states / carry-in states: [b][h][q][chunk][64p x 32n]
__device__ __align__(1024) float g_hch[BATCH*NHEADS*4*NCHUNK*64*32];
__device__ __align__(1024) __nv_bfloat16 g_xh [ROWS*DMODEL];
__device__ __align__(1024) __nv_bfloat16 g_xl [ROWS*DMODEL];
__device__ __align__(1024) __nv_bfloat16 g_w1h[DINPROJ*DMODEL];
__device__ __align__(1024) __nv_bfloat16 g_w1l[DINPROJ*DMODEL];
__device__ __align__(1024) __nv_bfloat16 g_w2h[DMODEL*DINNER];
__device__ __align__(1024) __nv_bfloat16 g_w2l[DMODEL*DINNER];
__device__ __align__(1024) __nv_bfloat16 g_ynh[ROWS*DINNER];
__device__ __align__(1024) __nv_bfloat16 g_ynl[ROWS*DINNER];

// ---------------- packed f32x2 helpers ----------------
__device__ __forceinline__ float2 ffma2(float2 a, float2 b, float2 c) {
    float2 d;
    asm("fma.rn.f32x2 %0, %1, %2, %3;"
        : "=l"(reinterpret_cast<unsigned long long &>(d))
        : "l"(reinterpret_cast<const unsigned long long &>(a)),
          "l"(reinterpret_cast<const unsigned long long &>(b)),
          "l"(reinterpret_cast<const unsigned long long &>(c)));
    return d;
}
__device__ __forceinline__ float2 fmul2(float2 a, float2 b) {
    float2 d;
    asm("mul.rn.f32x2 %0, %1, %2;"
        : "=l"(reinterpret_cast<unsigned long long &>(d))
        : "l"(reinterpret_cast<const unsigned long long &>(a)),
          "l"(reinterpret_cast<const unsigned long long &>(b)));
    return d;
}

// ---------------- sm_80-era primitives ----------
__device__ __forceinline__ uint32_t smem_u32(const void* p) {
    uint32_t a;
    asm("{ .reg .u64 t; cvta.to.shared.u64 t, %1; cvt.u32.u64 %0, t; }" : "=r"(a) : "l"(p));
    return a;
}
__device__ __forceinline__ void cp16(uint32_t dst, const void* src) {
    asm volatile("cp.async.cg.shared.global [%0], [%1], 16;" :: "r"(dst), "l"(src));
}
__device__ __forceinline__ void cp_commit() { asm volatile("cp.async.commit_group;" ::: "memory"); }
template<int W> __device__ __forceinline__ void cp_wait() {
    asm volatile("cp.async.wait_group %0;" :: "n"(W) : "memory");
}
__device__ __forceinline__ void ldsm_x4(uint32_t& r0, uint32_t& r1, uint32_t& r2, uint32_t& r3, uint32_t a) {
    asm volatile("ldmatrix.sync.aligned.m8n8.x4.shared.b16 {%0,%1,%2,%3}, [%4];"
                 : "=r"(r0), "=r"(r1), "=r"(r2), "=r"(r3) : "r"(a));
}
__device__ __forceinline__ void mma_bf16(float* c, const uint32_t* a, uint32_t b0, uint32_t b1) {
    asm volatile(
        "mma.sync.aligned.m16n8k16.row.col.f32.bf16.bf16.f32 "
        "{%0,%1,%2,%3}, {%4,%5,%6,%7}, {%8,%9}, {%0,%1,%2,%3};"
        : "+f"(c[0]), "+f"(c[1]), "+f"(c[2]), "+f"(c[3])
        : "r"(a[0]), "r"(a[1]), "r"(a[2]), "r"(a[3]), "r"(b0), "r"(b1));
}

// =====================================================================
// Tensor-core GEMM via mma.sync (unchanged from R5)
// =====================================================================
#define BM 128
#define BN 128
#define KC 64
#define TILE_B   16384u
#define STAGE_B  (4u*TILE_B)
#define NSTAGE   3
#define SMEM_GEMM (NSTAGE*STAGE_B)

__device__ __forceinline__ uint32_t swz(int row, int seg) {
    return (uint32_t)(row * 128 + ((seg ^ (row & 7)) << 4));
}

template<bool RES>
__global__ __launch_bounds__(256, 1)
void gemm_mma(const __nv_bfloat16* __restrict__ Ahp, const __nv_bfloat16* __restrict__ Alp,
              const __nv_bfloat16* __restrict__ Bhp, const __nv_bfloat16* __restrict__ Blp,
              const float* __restrict__ resid, float* __restrict__ C,
              int N, int K)
{
    extern __shared__ __align__(1024) char smem[];
    const uint32_t sb = smem_u32(smem);

    const int tid = threadIdx.x;
    const int wid = tid >> 5, lane = tid & 31;
    const int wm = wid & 1, wn = wid >> 1;
    const int m0 = blockIdx.y * BM, n0 = blockIdx.x * BN;
    const int NC = K / KC;

    int lrow[4], lseg[4];
#pragma unroll
    for (int it = 0; it < 4; it++) {
        int idx = tid + it * 256;
        lrow[it] = idx >> 3;
        lseg[it] = idx & 7;
    }

    auto load_chunk = [&](int stage, int k0) {
        uint32_t s = sb + stage * STAGE_B;
#pragma unroll
        for (int it = 0; it < 4; it++) {
            int row = lrow[it], seg = lseg[it];
            uint32_t d = swz(row, seg);
            size_t aoff = (size_t)(m0 + row) * K + k0 + seg * 8;
            cp16(s + d,              Ahp + aoff);
            cp16(s + TILE_B + d,     Alp + aoff);
            int brow = n0 + row; if (brow >= N) brow = N - 1;
            size_t boff = (size_t)brow * K + k0 + seg * 8;
            cp16(s + 2 * TILE_B + d, Bhp + boff);
            cp16(s + 3 * TILE_B + d, Blp + boff);
        }
        cp_commit();
    };

    float acc[4][4][4];
#pragma unroll
    for (int mi = 0; mi < 4; mi++)
#pragma unroll
        for (int ni = 0; ni < 4; ni++)
#pragma unroll
            for (int q = 0; q < 4; q++) acc[mi][ni][q] = 0.f;

    const int lgrp = lane >> 3, lr = lane & 7;
    const int a_roff = lr + (lgrp & 1) * 8;
    const int a_koff = lgrp >> 1;
    const int b_roff = lr + (lgrp >> 1) * 8;
    const int b_koff = lgrp & 1;

    uint32_t ah[2][4][4], al[2][4][4], bh[2][4][2], bl[2][4][2];

    auto load_frags = [&](int buf, uint32_t s, int k16) {
        int k2 = k16 * 2;
#pragma unroll
        for (int mi = 0; mi < 4; mi++) {
            int row = wm * 64 + mi * 16 + a_roff;
            uint32_t ad = swz(row, k2 + a_koff);
            ldsm_x4(ah[buf][mi][0], ah[buf][mi][1], ah[buf][mi][2], ah[buf][mi][3], s + ad);
            ldsm_x4(al[buf][mi][0], al[buf][mi][1], al[buf][mi][2], al[buf][mi][3], s + TILE_B + ad);
        }
#pragma unroll
        for (int nj = 0; nj < 2; nj++) {
            int row = wn * 32 + nj * 16 + b_roff;
            uint32_t bd = swz(row, k2 + b_koff);
            uint32_t r0, r1, r2, r3;
            ldsm_x4(r0, r1, r2, r3, s + 2 * TILE_B + bd);
            bh[buf][nj * 2][0] = r0; bh[buf][nj * 2][1] = r1;
            bh[buf][nj * 2 + 1][0] = r2; bh[buf][nj * 2 + 1][1] = r3;
            ldsm_x4(r0, r1, r2, r3, s + 3 * TILE_B + bd);
            bl[buf][nj * 2][0] = r0; bl[buf][nj * 2][1] = r1;
            bl[buf][nj * 2 + 1][0] = r2; bl[buf][nj * 2 + 1][1] = r3;
        }
    };

    load_chunk(0, 0);
    load_chunk(1, KC);

    for (int c = 0; c < NC; c++) {
        if (c + 2 < NC) load_chunk((c + 2) % NSTAGE, (c + 2) * KC);
        else            cp_commit();
        cp_wait<2>();
        __syncthreads();

        uint32_t s = sb + (c % NSTAGE) * STAGE_B;
        load_frags(0, s, 0);
#pragma unroll
        for (int k16 = 0; k16 < 4; k16++) {
            if (k16 < 3) load_frags((k16 + 1) & 1, s, k16 + 1);
            const int bb = k16 & 1;
#pragma unroll
            for (int mi = 0; mi < 4; mi++)
#pragma unroll
                for (int ni = 0; ni < 4; ni++) {
                    mma_bf16(acc[mi][ni], ah[bb][mi], bh[bb][ni][0], bh[bb][ni][1]);
                    mma_bf16(acc[mi][ni], ah[bb][mi], bl[bb][ni][0], bl[bb][ni][1]);
                    mma_bf16(acc[mi][ni], al[bb][mi], bh[bb][ni][0], bh[bb][ni][1]);
                }
        }
        __syncthreads();
    }

    const int quad = lane >> 2, qt = lane & 3;
#pragma unroll
    for (int mi = 0; mi < 4; mi++) {
#pragma unroll
        for (int ni = 0; ni < 4; ni++) {
            int gm = m0 + wm * 64 + mi * 16 + quad;
            int gn = n0 + wn * 32 + ni * 8 + qt * 2;
            if (gn < N) {
                {
                    float2 v = make_float2(acc[mi][ni][0], acc[mi][ni][1]);
                    size_t o = (size_t)gm * N + gn;
                    if (RES) { float2 rv = *(const float2*)(resid + o); v.x += rv.x; v.y += rv.y; }
                    *(float2*)(C + o) = v;
                }
                {
                    float2 v = make_float2(acc[mi][ni][2], acc[mi][ni][3]);
                    size_t o = (size_t)(gm + 8) * N + gn;
                    if (RES) { float2 rv = *(const float2*)(resid + o); v.x += rv.x; v.y += rv.y; }
                    *(float2*)(C + o) = v;
                }
            }
        }
    }
}

// =====================================================================
// merged fp32 -> bf16 hi/lo split (one launch)
// =====================================================================
#define N4_X  (ROWS*DMODEL/4)
#define N4_W1 (DINPROJ*DMODEL/4)
#define N4_W2 (DMODEL*DINNER/4)

__device__ __forceinline__ void split4(float4 v, __nv_bfloat162* hi, __nv_bfloat162* lo, int i) {
    __nv_bfloat16 hx = __float2bfloat16(v.x);
    __nv_bfloat16 hy = __float2bfloat16(v.y);
    __nv_bfloat16 hz = __float2bfloat16(v.z);
    __nv_bfloat16 hw = __float2bfloat16(v.w);
    hi[i * 2]     = __halves2bfloat162(hx, hy);
    hi[i * 2 + 1] = __halves2bfloat162(hz, hw);
    lo[i * 2]     = __halves2bfloat162(__float2bfloat16(v.x - __bfloat162float(hx)),
                                       __float2bfloat16(v.y - __bfloat162float(hy)));
    lo[i * 2 + 1] = __halves2bfloat162(__float2bfloat16(v.z - __bfloat162float(hz)),
                                       __float2bfloat16(v.w - __bfloat162float(hw)));
}

__global__ __launch_bounds__(256)
void cvt_all(const float4* __restrict__ x, const float4* __restrict__ w1,
             const float4* __restrict__ w2)
{
    int i = blockIdx.x * 256 + threadIdx.x;
    if (i < N4_X) {
        split4(x[i], (__nv_bfloat162*)g_xh, (__nv_bfloat162*)g_xl, i);
    } else if (i < N4_X + N4_W1) {
        int j = i - N4_X;
        split4(w1[j], (__nv_bfloat162*)g_w1h, (__nv_bfloat162*)g_w1l, j);
    } else if (i < N4_X + N4_W1 + N4_W2) {
        int j = i - N4_X - N4_W1;
        split4(w2[j], (__nv_bfloat162*)g_w2h, (__nv_bfloat162*)g_w2l, j);
    }
}

// =====================================================================
// Causal depthwise conv + SiLU; dt softplus; dA
// =====================================================================
__global__ __launch_bounds__(256)
void conv_act_kernel(const float* __restrict__ conv_w, const float* __restrict__ conv_b,
                     const float* __restrict__ dt_bias, const float* __restrict__ A_log)
{
    const int c  = blockIdx.x * 256 + threadIdx.x;
    const int tb = blockIdx.y * 4;
    const int b  = blockIdx.z;

    float w0 = conv_w[c * 4 + 0], w1 = conv_w[c * 4 + 1];
    float w2 = conv_w[c * 4 + 2], w3 = conv_w[c * 4 + 3];
    float bias = conv_b[c];

    float v[7];
#pragma unroll
    for (int k = 0; k < 7; k++) {
        int tt = tb - 3 + k;
        v[k] = (tt >= 0) ? g_zx[((size_t)b * SEQLEN + tt) * DINPROJ + DINNER + c] : 0.f;
    }
#pragma unroll
    for (int i = 0; i < 4; i++) {
        float a = bias + v[i] * w0 + v[i + 1] * w1 + v[i + 2] * w2 + v[i + 3] * w3;
        g_xbc[((size_t)b * SEQLEN + tb + i) * CONVDIM + c] = a / (1.f + expf(-a));
    }
    if (blockIdx.x == 0 && threadIdx.x < NHEADS) {
        int hh = threadIdx.x;
        float negA = -expf(A_log[hh]);
        float bth  = dt_bias[hh];
#pragma unroll
        for (int i = 0; i < 4; i++) {
            size_t row = (size_t)b * SEQLEN + tb + i;
            float raw = g_zx[row * DINPROJ + (DINNER + CONVDIM) + hh] + bth;
            float dtv = (raw > 20.f) ? raw : log1pf(expf(raw));
            g_dt[row * NHEADS + hh] = dtv;
            g_dA[row * NHEADS + hh] = expf(dtv * negA);
        }
    }
}

// =====================================================================
// Pass A: chunked local scan. grid (NHEADS, BATCH, NCHUNK*4) = 1024 blocks.
// z = chunk*4 + q. Local scan from h=0 over CLEN steps; writes y_local,
// tracks cumP (q==0 writes g_cum), stores end-state to g_hch.
// =====================================================================
__global__ __launch_bounds__(256)
void scan_chunk_kernel()
{
    const int h = blockIdx.x, b = blockIdx.y;
    const int chunk = blockIdx.z >> 2, q = blockIdx.z & 3;
    const int tid = threadIdx.x;
    const int p = tid >> 2, ns = tid & 3;
    const int nbase = q * 32;
    const int T0 = chunk * CLEN;
    const bool wr_cum = ((blockIdx.z & 3) == 0) && (tid == 0);
    float* __restrict__ yout = (q == 0) ? g_yp0 : (q == 1) ? g_yp1 : (q == 2) ? g_yp2 : g_yp3;

    __shared__ __align__(16) float sB[8][32];
    __shared__ __align__(16) float sC[8][32];
    __shared__ __align__(16) float sX[8][64];
    __shared__ float sdA[8], sdt[8];

    float2 hs[4];
#pragma unroll
    for (int j = 0; j < 4; j++) hs[j] = make_float2(0.f, 0.f);
    float cum = 1.f;

    for (int t0 = T0; t0 < T0 + CLEN; t0 += 8) {
        __syncthreads();
        {
            int idx = tid;
            if (idx < 64) {
                int s = idx >> 3, f = idx & 7;
                size_t row = ((size_t)b * SEQLEN + t0 + s) * CONVDIM;
                *(float4*)&sB[s][f * 4] = *(const float4*)&g_xbc[row + DINNER + nbase + f * 4];
            } else if (idx < 128) {
                int r = idx - 64; int s = r >> 3, f = r & 7;
                size_t row = ((size_t)b * SEQLEN + t0 + s) * CONVDIM;
                *(float4*)&sC[s][f * 4] = *(const float4*)&g_xbc[row + DINNER + DSTATE + nbase + f * 4];
            } else {
                int r = idx - 128; int s = r >> 4, f = r & 15;
                size_t row = ((size_t)b * SEQLEN + t0 + s) * CONVDIM;
                *(float4*)&sX[s][f * 4] = *(const float4*)&g_xbc[row + h * HEADDIM + f * 4];
            }
            if (tid < 16) {
                int s = tid & 7;
                size_t r = ((size_t)b * SEQLEN + t0 + s) * NHEADS + h;
                if (tid < 8) sdA[s] = g_dA[r];
                else         sdt[s] = g_dt[r];
            }
        }
        __syncthreads();

#pragma unroll
        for (int s = 0; s < 8; s++) {
            float dAv = sdA[s];
            cum *= dAv;
            float2 dA2 = make_float2(dAv, dAv);
            float coef = sdt[s] * sX[s][p];
            float2 c2  = make_float2(coef, coef);
            float4 B0 = *(const float4*)&sB[s][ns * 4];
            float4 B1 = *(const float4*)&sB[s][ns * 4 + 16];
            float4 C0 = *(const float4*)&sC[s][ns * 4];
            float4 C1 = *(const float4*)&sC[s][ns * 4 + 16];
            float2 acc = make_float2(0.f, 0.f);
            hs[0] = ffma2(hs[0], dA2, fmul2(c2, make_float2(B0.x, B0.y)));
            acc   = ffma2(hs[0], make_float2(C0.x, C0.y), acc);
            hs[1] = ffma2(hs[1], dA2, fmul2(c2, make_float2(B0.z, B0.w)));
            acc   = ffma2(hs[1], make_float2(C0.z, C0.w), acc);
            hs[2] = ffma2(hs[2], dA2, fmul2(c2, make_float2(B1.x, B1.y)));
            acc   = ffma2(hs[2], make_float2(C1.x, C1.y), acc);
            hs[3] = ffma2(hs[3], dA2, fmul2(c2, make_float2(B1.z, B1.w)));
            acc   = ffma2(hs[3], make_float2(C1.z, C1.w), acc);
            float y = acc.x + acc.y;
            y += __shfl_down_sync(0xffffffffu, y, 2, 4);
            y += __shfl_down_sync(0xffffffffu, y, 1, 4);
            if (ns == 0)
                yout[((size_t)b * SEQLEN + t0 + s) * DINNER + h * HEADDIM + p] = y;
            if (wr_cum)
                g_cum[((size_t)b * SEQLEN + t0 + s) * NHEADS + h] = cum;
        }
    }

    // store end-state in canonical [p][n_local] layout
    float* hdst = &g_hch[(size_t)((((b * NHEADS + h) * 4) + q) * NCHUNK + chunk) * (64 * 32)];
    *(float2*)&hdst[p * 32 + ns * 4]          = hs[0];
    *(float2*)&hdst[p * 32 + ns * 4 + 2]      = hs[1];
    *(float2*)&hdst[p * 32 + 16 + ns * 4]     = hs[2];
    *(float2*)&hdst[p * 32 + 16 + ns * 4 + 2] = hs[3];
}

// =====================================================================
// Pass B1: propagate chunk-boundary states.
// h0_1 = hend0 ; h0_2 = Pi1*h0_1 + hend1 ; h0_3 = Pi2*h0_2 + hend2
// Pi_c = g_cum at (t = c*CLEN + CLEN-1). Results overwrite g_hch slots 1..3.
// =====================================================================
__global__ __launch_bounds__(256)
void propagate_kernel()
{
    const int h = blockIdx.x, b = blockIdx.y, q = blockIdx.z;
    const int tid = threadIdx.x;
    float* base = &g_hch[(size_t)((((b * NHEADS + h) * 4) + q) * NCHUNK) * (64 * 32)];
    const int off = tid * 8;

    float Pi1 = g_cum[((size_t)b * SEQLEN + 1 * CLEN + CLEN - 1) * NHEADS + h];
    float Pi2 = g_cum[((size_t)b * SEQLEN + 2 * CLEN + CLEN - 1) * NHEADS + h];

    float4 e0a = *(float4*)&base[0 * 2048 + off],     e0b = *(float4*)&base[0 * 2048 + off + 4];
    float4 e1a = *(float4*)&base[1 * 2048 + off],     e1b = *(float4*)&base[1 * 2048 + off + 4];
    float4 e2a = *(float4*)&base[2 * 2048 + off],     e2b = *(float4*)&base[2 * 2048 + off + 4];

    // h0 for chunk 1
    float4 h1a = e0a, h1b = e0b;
    // h0 for chunk 2
    float4 h2a, h2b;
    h2a.x = Pi1 * h1a.x + e1a.x; h2a.y = Pi1 * h1a.y + e1a.y;
    h2a.z = Pi1 * h1a.z + e1a.z; h2a.w = Pi1 * h1a.w + e1a.w;
    h2b.x = Pi1 * h1b.x + e1b.x; h2b.y = Pi1 * h1b.y + e1b.y;
    h2b.z = Pi1 * h1b.z + e1b.z; h2b.w = Pi1 * h1b.w + e1b.w;
    // h0 for chunk 3
    float4 h3a, h3b;
    h3a.x = Pi2 * h2a.x + e2a.x; h3a.y = Pi2 * h2a.y + e2a.y;
    h3a.z = Pi2 * h2a.z + e2a.z; h3a.w = Pi2 * h2a.w + e2a.w;
    h3b.x = Pi2 * h2b.x + e2b.x; h3b.y = Pi2 * h2b.y + e2b.y;
    h3b.z = Pi2 * h2b.z + e2b.z; h3b.w = Pi2 * h2b.w + e2b.w;

    *(float4*)&base[1 * 2048 + off] = h1a; *(float4*)&base[1 * 2048 + off + 4] = h1b;
    *(float4*)&base[2 * 2048 + off] = h2a; *(float4*)&base[2 * 2048 + off + 4] = h2b;
    *(float4*)&base[3 * 2048 + off] = h3a; *(float4*)&base[3 * 2048 + off + 4] = h3b;
}

// =====================================================================
// Pass B2: correction y_t += cumP_t * (C_t . h0) for chunks 1..3.
// grid (NHEADS, BATCH, 12): chunk = 1 + z/4, q = z%4.
// =====================================================================
__global__ __launch_bounds__(256)
void correct_kernel()
{
    const int h = blockIdx.x, b = blockIdx.y;
    const int chunk = 1 + (blockIdx.z >> 2), q = blockIdx.z & 3;
    const int tid = threadIdx.x;
    const int p = tid >> 2, ns = tid & 3;
    const int nbase = q * 32;
    float* __restrict__ yout = (q == 0) ? g_yp0 : (q == 1) ? g_yp1 : (q == 2) ? g_yp2 : g_yp3;

    const float* h0 = &g_hch[(size_t)((((b * NHEADS + h) * 4) + q) * NCHUNK + chunk) * (64 * 32)];
    float4 H0 = *(const float4*)&h0[p * 32 + ns * 4];
    float4 H1 = *(const float4*)&h0[p * 32 + 16 + ns * 4];

    __shared__ __align__(16) float sC[8][32];
    __shared__ float scum[8];

    const int T0 = chunk * CLEN;
    for (int t0 = T0; t0 < T0 + CLEN; t0 += 8) {
        __syncthreads();
        if (tid < 64) {
            int s = tid >> 3, f = tid & 7;
            size_t row = ((size_t)b * SEQLEN + t0 + s) * CONVDIM;
            *(float4*)&sC[s][f * 4] = *(const float4*)&g_xbc[row + DINNER + DSTATE + nbase + f * 4];
        } else if (tid < 72) {
            int s = tid - 64;
            scum[s] = g_cum[((size_t)b * SEQLEN + t0 + s) * NHEADS + h];
        }
        __syncthreads();

#pragma unroll
        for (int s = 0; s < 8; s++) {
            float4 C0 = *(const float4*)&sC[s][ns * 4];
            float4 C1 = *(const float4*)&sC[s][16 + ns * 4];
            float acc = H0.x * C0.x + H0.y * C0.y + H0.z * C0.z + H0.w * C0.w
                      + H1.x * C1.x + H1.y * C1.y + H1.z * C1.z + H1.w * C1.w;
            acc += __shfl_down_sync(0xffffffffu, acc, 2, 4);
            acc += __shfl_down_sync(0xffffffffu, acc, 1, 4);
            if (ns == 0) {
                size_t o = ((size_t)b * SEQLEN + t0 + s) * DINNER + h * HEADDIM + p;
                yout[o] += scum[s] * acc;
            }
        }
    }
}

// =====================================================================
// skip + gate + RMSNorm -> bf16 hi/lo for GEMM2
// =====================================================================
__global__ __launch_bounds__(256)
void gate_norm_kernel(const float* __restrict__ Dw, const float* __restrict__ norm_w)
{
    const int t = blockIdx.x;
    const int b = blockIdx.y;
    const size_t row = (size_t)b * SEQLEN + t;
    const float4* __restrict__ z4 = (const float4*)&g_zx [row * DINPROJ];
    const float4* __restrict__ x4 = (const float4*)&g_xbc[row * CONVDIM];
    const float4* __restrict__ y0 = (const float4*)&g_yp0[row * DINNER];
    const float4* __restrict__ y1 = (const float4*)&g_yp1[row * DINNER];
    const float4* __restrict__ y2 = (const float4*)&g_yp2[row * DINNER];
    const float4* __restrict__ y3 = (const float4*)&g_yp3[row * DINNER];

    float4 vals[2];
    float ss = 0.f;
#pragma unroll
    for (int r = 0; r < 2; r++) {
        int f = r * 256 + threadIdx.x;
        float dv = Dw[f >> 4];
        float4 a = y0[f], bq = y1[f], cq = y2[f], dq = y3[f], xv = x4[f], zv = z4[f];
        float4 v;
        v.x = a.x + bq.x + cq.x + dq.x + dv * xv.x;
        v.y = a.y + bq.y + cq.y + dq.y + dv * xv.y;
        v.z = a.z + bq.z + cq.z + dq.z + dv * xv.z;
        v.w = a.w + bq.w + cq.w + dq.w + dv * xv.w;
        v.x *= zv.x / (1.f + expf(-zv.x));
        v.y *= zv.y / (1.f + expf(-zv.y));
        v.z *= zv.z / (1.f + expf(-zv.z));
        v.w *= zv.w / (1.f + expf(-zv.w));
        vals[r] = v;
        ss += v.x * v.x + v.y * v.y + v.z * v.z + v.w * v.w;
    }
    __shared__ float red[256];
    red[threadIdx.x] = ss;
    __syncthreads();
    for (int off = 128; off > 0; off >>= 1) {
        if (threadIdx.x < off) red[threadIdx.x] += red[threadIdx.x + off];
        __syncthreads();
    }
    float scale = rsqrtf(red[0] / (float)DINNER + EPS);
    __nv_bfloat162* outh = (__nv_bfloat162*)&g_ynh[row * DINNER];
    __nv_bfloat162* outl = (__nv_bfloat162*)&g_ynl[row * DINNER];
    const float4* nw4 = (const float4*)norm_w;
#pragma unroll
    for (int r = 0; r < 2; r++) {
        int f = r * 256 + threadIdx.x;
        float4 w = nw4[f];
        float4 v = vals[r];
        v.x *= scale * w.x; v.y *= scale * w.y; v.z *= scale * w.z; v.w *= scale * w.w;
        split4(v, outh, outl, f);
    }
}

// =====================================================================
extern "C" void kernel_launch(void* const* d_in, const int* in_sizes, int n_in,
                              void* d_out, int out_size)
{
    const float* x          = (const float*)d_in[0];
    const float* in_proj_w  = (const float*)d_in[1];
    const float* conv_w     = (const float*)d_in[2];
    const float* conv_b     = (const float*)d_in[3];
    const float* dt_bias    = (const float*)d_in[4];
    const float* A_log      = (const float*)d_in[5];
    const float* Dw         = (const float*)d_in[6];
    const float* norm_w     = (const float*)d_in[7];
    const float* out_proj_w = (const float*)d_in[8];
    float* out = (float*)d_out;

    float *p_zx = nullptr;
    void *p_xh, *p_xl, *p_w1h, *p_w1l, *p_w2h, *p_w2l, *p_ynh, *p_ynl;
    cudaGetSymbolAddress((void**)&p_zx, g_zx);
    cudaGetSymbolAddress(&p_xh,  g_xh);  cudaGetSymbolAddress(&p_xl,  g_xl);
    cudaGetSymbolAddress(&p_w1h, g_w1h); cudaGetSymbolAddress(&p_w1l, g_w1l);
    cudaGetSymbolAddress(&p_w2h, g_w2h); cudaGetSymbolAddress(&p_w2l, g_w2l);
    cudaGetSymbolAddress(&p_ynh, g_ynh); cudaGetSymbolAddress(&p_ynl, g_ynl);

    cudaFuncSetAttribute(gemm_mma<false>, cudaFuncAttributeMaxDynamicSharedMemorySize, SMEM_GEMM);
    cudaFuncSetAttribute(gemm_mma<true>,  cudaFuncAttributeMaxDynamicSharedMemorySize, SMEM_GEMM);

    // 0) fp32 -> bf16 hi/lo conversions
    {
        int total4 = N4_X + N4_W1 + N4_W2;
        cvt_all<<<(total4 + 255)/256, 256>>>(
            (const float4*)x, (const float4*)in_proj_w, (const float4*)out_proj_w);
    }

    // 1) zxbcdt = x @ in_proj_w^T
    gemm_mma<false><<<dim3((DINPROJ + BN - 1)/BN, ROWS/BM), 256, SMEM_GEMM>>>(
        (const __nv_bfloat16*)p_xh, (const __nv_bfloat16*)p_xl,
        (const __nv_bfloat16*)p_w1h, (const __nv_bfloat16*)p_w1l,
        nullptr, p_zx, DINPROJ, DMODEL);

    // 2) conv + SiLU; dt/dA
    conv_act_kernel<<<dim3(CONVDIM/256, SEQLEN/4, BATCH), 256>>>(conv_w, conv_b, dt_bias, A_log);

    // 3) chunked selective scan
    scan_chunk_kernel<<<dim3(NHEADS, BATCH, NCHUNK * 4), 256>>>();
    propagate_kernel<<<dim3(NHEADS, BATCH, 4), 256>>>();
    correct_kernel<<<dim3(NHEADS, BATCH, (NCHUNK - 1) * 4), 256>>>();

    // 4) skip + gate + RMSNorm
    gate_norm_kernel<<<dim3(SEQLEN, BATCH), 256>>>(Dw, norm_w);

    // 5) out = x + yn @ out_proj_w^T
    gemm_mma<true><<<dim3(DMODEL/BN, ROWS/BM), 256, SMEM_GEMM>>>(
        (const __nv_bfloat16*)p_ynh, (const __nv_bfloat16*)p_ynl,
        (const __nv_bfloat16*)p_w2h, (const __nv_bfloat16*)p_w2l,
        x, out, DMODEL, DINNER);
}

// round 7
// speedup vs baseline: 1.3861x; 1.3861x over previous
#include <cuda_runtime.h>
#include <cuda_bf16.h>
#include <math.h>
#include <stdint.h>

// ---------------- problem constants ----------------
#define BATCH    2
#define SEQLEN   1024
#define DMODEL   1024
#define DINNER   2048
#define NHEADS   32
#define HEADDIM  64
#define DSTATE   128
#define DCONV    4
#define CONVDIM  2304
#define DINPROJ  4384
#define ROWS     (BATCH*SEQLEN)
#define EPS      1e-5f
#define CLEN     64
#define NCH      (SEQLEN/CLEN)     // 16 chunks

// ---------------- scratch ----------------
__device__ __align__(1024) float g_zx [ROWS*DINPROJ];
__device__ __align__(1024) float g_xbc[ROWS*CONVDIM];
__device__ __align__(1024) float g_dt [ROWS*NHEADS];
__device__ __align__(1024) float g_y  [ROWS*DINNER];
__device__ __align__(1024) float g_hc [BATCH*NHEADS*NCH*HEADDIM*DSTATE]; // per-chunk contribs
__device__ __align__(1024) float g_h0 [BATCH*NHEADS*NCH*HEADDIM*DSTATE]; // carry-in states
__device__ __align__(1024) float g_pi [BATCH*NHEADS*NCH];                // sdt total per chunk
__device__ __align__(1024) __nv_bfloat16 g_xh [ROWS*DMODEL];
__device__ __align__(1024) __nv_bfloat16 g_xl [ROWS*DMODEL];
__device__ __align__(1024) __nv_bfloat16 g_w1h[DINPROJ*DMODEL];
__device__ __align__(1024) __nv_bfloat16 g_w1l[DINPROJ*DMODEL];
__device__ __align__(1024) __nv_bfloat16 g_w2h[DMODEL*DINNER];
__device__ __align__(1024) __nv_bfloat16 g_w2l[DMODEL*DINNER];
__device__ __align__(1024) __nv_bfloat16 g_ynh[ROWS*DINNER];
__device__ __align__(1024) __nv_bfloat16 g_ynl[ROWS*DINNER];

// ---------------- primitives ----------------
__device__ __forceinline__ uint32_t smem_u32(const void* p) {
    uint32_t a;
    asm("{ .reg .u64 t; cvta.to.shared.u64 t, %1; cvt.u32.u64 %0, t; }" : "=r"(a) : "l"(p));
    return a;
}
__device__ __forceinline__ void cp16(uint32_t dst, const void* src) {
    asm volatile("cp.async.cg.shared.global [%0], [%1], 16;" :: "r"(dst), "l"(src));
}
__device__ __forceinline__ void cp_commit() { asm volatile("cp.async.commit_group;" ::: "memory"); }
template<int W> __device__ __forceinline__ void cp_wait() {
    asm volatile("cp.async.wait_group %0;" :: "n"(W) : "memory");
}
__device__ __forceinline__ void ldsm_x4(uint32_t& r0, uint32_t& r1, uint32_t& r2, uint32_t& r3, uint32_t a) {
    asm volatile("ldmatrix.sync.aligned.m8n8.x4.shared.b16 {%0,%1,%2,%3}, [%4];"
                 : "=r"(r0), "=r"(r1), "=r"(r2), "=r"(r3) : "r"(a));
}
__device__ __forceinline__ void mma_bf16(float* c, const uint32_t* a, uint32_t b0, uint32_t b1) {
    asm volatile(
        "mma.sync.aligned.m16n8k16.row.col.f32.bf16.bf16.f32 "
        "{%0,%1,%2,%3}, {%4,%5,%6,%7}, {%8,%9}, {%0,%1,%2,%3};"
        : "+f"(c[0]), "+f"(c[1]), "+f"(c[2]), "+f"(c[3])
        : "r"(a[0]), "r"(a[1]), "r"(a[2]), "r"(a[3]), "r"(b0), "r"(b1));
}
__device__ __forceinline__ uint32_t swz(int row, int seg) {
    return (uint32_t)(row * 128 + ((seg ^ (row & 7)) << 4));
}
// swizzled byte offset for arbitrary byte column within a 128B row
__device__ __forceinline__ uint32_t swzb(int row, int colb) {
    return (uint32_t)(row * 128 + (((colb >> 4) ^ (row & 7)) << 4) + (colb & 15));
}
__device__ __forceinline__ void hilo(float v, __nv_bfloat16& h, __nv_bfloat16& l) {
    h = __float2bfloat16(v);
    l = __float2bfloat16(v - __bfloat162float(h));
}

// =====================================================================
// Tensor-core GEMM (verified; unchanged from R5)
// =====================================================================
#define BM 128
#define BN 128
#define KC 64
#define TILE_B   16384u
#define STAGE_B  (4u*TILE_B)
#define NSTAGE   3
#define SMEM_GEMM (NSTAGE*STAGE_B)

template<bool RES>
__global__ __launch_bounds__(256, 1)
void gemm_mma(const __nv_bfloat16* __restrict__ Ahp, const __nv_bfloat16* __restrict__ Alp,
              const __nv_bfloat16* __restrict__ Bhp, const __nv_bfloat16* __restrict__ Blp,
              const float* __restrict__ resid, float* __restrict__ C,
              int N, int K)
{
    extern __shared__ __align__(1024) char smem[];
    const uint32_t sb = smem_u32(smem);

    const int tid = threadIdx.x;
    const int wid = tid >> 5, lane = tid & 31;
    const int wm = wid & 1, wn = wid >> 1;
    const int m0 = blockIdx.y * BM, n0 = blockIdx.x * BN;
    const int NC = K / KC;

    int lrow[4], lseg[4];
#pragma unroll
    for (int it = 0; it < 4; it++) {
        int idx = tid + it * 256;
        lrow[it] = idx >> 3;
        lseg[it] = idx & 7;
    }

    auto load_chunk = [&](int stage, int k0) {
        uint32_t s = sb + stage * STAGE_B;
#pragma unroll
        for (int it = 0; it < 4; it++) {
            int row = lrow[it], seg = lseg[it];
            uint32_t d = swz(row, seg);
            size_t aoff = (size_t)(m0 + row) * K + k0 + seg * 8;
            cp16(s + d,              Ahp + aoff);
            cp16(s + TILE_B + d,     Alp + aoff);
            int brow = n0 + row; if (brow >= N) brow = N - 1;
            size_t boff = (size_t)brow * K + k0 + seg * 8;
            cp16(s + 2 * TILE_B + d, Bhp + boff);
            cp16(s + 3 * TILE_B + d, Blp + boff);
        }
        cp_commit();
    };

    float acc[4][4][4];
#pragma unroll
    for (int mi = 0; mi < 4; mi++)
#pragma unroll
        for (int ni = 0; ni < 4; ni++)
#pragma unroll
            for (int q = 0; q < 4; q++) acc[mi][ni][q] = 0.f;

    const int lgrp = lane >> 3, lr = lane & 7;
    const int a_roff = lr + (lgrp & 1) * 8;
    const int a_koff = lgrp >> 1;
    const int b_roff = lr + (lgrp >> 1) * 8;
    const int b_koff = lgrp & 1;

    load_chunk(0, 0);
    load_chunk(1, KC);

    for (int c = 0; c < NC; c++) {
        if (c + 2 < NC) load_chunk((c + 2) % NSTAGE, (c + 2) * KC);
        else            cp_commit();
        cp_wait<2>();
        __syncthreads();

        uint32_t s = sb + (c % NSTAGE) * STAGE_B;
#pragma unroll
        for (int k16 = 0; k16 < 4; k16++) {
            int k2 = k16 * 2;
            uint32_t ah[4][4], al[4][4], bh[4][2], bl[4][2];
#pragma unroll
            for (int mi = 0; mi < 4; mi++) {
                int row = wm * 64 + mi * 16 + a_roff;
                uint32_t ad = swz(row, k2 + a_koff);
                ldsm_x4(ah[mi][0], ah[mi][1], ah[mi][2], ah[mi][3], s + ad);
                ldsm_x4(al[mi][0], al[mi][1], al[mi][2], al[mi][3], s + TILE_B + ad);
            }
#pragma unroll
            for (int nj = 0; nj < 2; nj++) {
                int row = wn * 32 + nj * 16 + b_roff;
                uint32_t bd = swz(row, k2 + b_koff);
                uint32_t r0, r1, r2, r3;
                ldsm_x4(r0, r1, r2, r3, s + 2 * TILE_B + bd);
                bh[nj * 2][0] = r0; bh[nj * 2][1] = r1;
                bh[nj * 2 + 1][0] = r2; bh[nj * 2 + 1][1] = r3;
                ldsm_x4(r0, r1, r2, r3, s + 3 * TILE_B + bd);
                bl[nj * 2][0] = r0; bl[nj * 2][1] = r1;
                bl[nj * 2 + 1][0] = r2; bl[nj * 2 + 1][1] = r3;
            }
#pragma unroll
            for (int mi = 0; mi < 4; mi++)
#pragma unroll
                for (int ni = 0; ni < 4; ni++) {
                    mma_bf16(acc[mi][ni], ah[mi], bh[ni][0], bh[ni][1]);
                    mma_bf16(acc[mi][ni], ah[mi], bl[ni][0], bl[ni][1]);
                    mma_bf16(acc[mi][ni], al[mi], bh[ni][0], bh[ni][1]);
                }
        }
        __syncthreads();
    }

    const int quad = lane >> 2, qt = lane & 3;
#pragma unroll
    for (int mi = 0; mi < 4; mi++) {
#pragma unroll
        for (int ni = 0; ni < 4; ni++) {
            int gm = m0 + wm * 64 + mi * 16 + quad;
            int gn = n0 + wn * 32 + ni * 8 + qt * 2;
            if (gn < N) {
                {
                    float2 v = make_float2(acc[mi][ni][0], acc[mi][ni][1]);
                    size_t o = (size_t)gm * N + gn;
                    if (RES) { float2 rv = *(const float2*)(resid + o); v.x += rv.x; v.y += rv.y; }
                    *(float2*)(C + o) = v;
                }
                {
                    float2 v = make_float2(acc[mi][ni][2], acc[mi][ni][3]);
                    size_t o = (size_t)(gm + 8) * N + gn;
                    if (RES) { float2 rv = *(const float2*)(resid + o); v.x += rv.x; v.y += rv.y; }
                    *(float2*)(C + o) = v;
                }
            }
        }
    }
}

// =====================================================================
// merged fp32 -> bf16 hi/lo split
// =====================================================================
#define N4_X  (ROWS*DMODEL/4)
#define N4_W1 (DINPROJ*DMODEL/4)
#define N4_W2 (DMODEL*DINNER/4)

__device__ __forceinline__ void split4(float4 v, __nv_bfloat162* hi, __nv_bfloat162* lo, int i) {
    __nv_bfloat16 hx, lx, hy, ly, hz, lz, hw, lw;
    hilo(v.x, hx, lx); hilo(v.y, hy, ly); hilo(v.z, hz, lz); hilo(v.w, hw, lw);
    hi[i * 2]     = __halves2bfloat162(hx, hy);
    hi[i * 2 + 1] = __halves2bfloat162(hz, hw);
    lo[i * 2]     = __halves2bfloat162(lx, ly);
    lo[i * 2 + 1] = __halves2bfloat162(lz, lw);
}

__global__ __launch_bounds__(256)
void cvt_all(const float4* __restrict__ x, const float4* __restrict__ w1,
             const float4* __restrict__ w2)
{
    int i = blockIdx.x * 256 + threadIdx.x;
    if (i < N4_X) {
        split4(x[i], (__nv_bfloat162*)g_xh, (__nv_bfloat162*)g_xl, i);
    } else if (i < N4_X + N4_W1) {
        int j = i - N4_X;
        split4(w1[j], (__nv_bfloat162*)g_w1h, (__nv_bfloat162*)g_w1l, j);
    } else if (i < N4_X + N4_W1 + N4_W2) {
        int j = i - N4_X - N4_W1;
        split4(w2[j], (__nv_bfloat162*)g_w2h, (__nv_bfloat162*)g_w2l, j);
    }
}

// =====================================================================
// Causal depthwise conv + SiLU; dt softplus
// =====================================================================
__global__ __launch_bounds__(256)
void conv_act_kernel(const float* __restrict__ conv_w, const float* __restrict__ conv_b,
                     const float* __restrict__ dt_bias)
{
    const int c  = blockIdx.x * 256 + threadIdx.x;
    const int tb = blockIdx.y * 4;
    const int b  = blockIdx.z;

    float w0 = conv_w[c * 4 + 0], w1 = conv_w[c * 4 + 1];
    float w2 = conv_w[c * 4 + 2], w3 = conv_w[c * 4 + 3];
    float bias = conv_b[c];

    float v[7];
#pragma unroll
    for (int k = 0; k < 7; k++) {
        int tt = tb - 3 + k;
        v[k] = (tt >= 0) ? g_zx[((size_t)b * SEQLEN + tt) * DINPROJ + DINNER + c] : 0.f;
    }
#pragma unroll
    for (int i = 0; i < 4; i++) {
        float a = bias + v[i] * w0 + v[i + 1] * w1 + v[i + 2] * w2 + v[i + 3] * w3;
        g_xbc[((size_t)b * SEQLEN + tb + i) * CONVDIM + c] = a / (1.f + expf(-a));
    }
    if (blockIdx.x == 0 && threadIdx.x < NHEADS) {
        int hh = threadIdx.x;
        float bth = dt_bias[hh];
#pragma unroll
        for (int i = 0; i < 4; i++) {
            size_t row = (size_t)b * SEQLEN + tb + i;
            float raw = g_zx[row * DINPROJ + (DINNER + CONVDIM) + hh] + bth;
            g_dt[row * NHEADS + hh] = (raw > 20.f) ? raw : log1pf(expf(raw));
        }
    }
}

// =====================================================================
// SSD phase 1: per-chunk local attention-form scan on tensor cores.
// grid (NCH, BATCH, NHEADS), 256 threads.
// smem panels (bf16, SW-swizzled 128B rows):
//   Cp[2][64][64], Bp[2][64][64]  (t-major, K=n panels)
//   Bt[128][64]                   (n-major, K=s)
//   Ut[64][64], Uw[64][64]        (p-major, K=s)
//   G [64][64]                    (t-major, K=s)
// =====================================================================
#define OFF_CPH 0u
#define OFF_CPL 16384u
#define OFF_BPH 32768u
#define OFF_BPL 49152u
#define OFF_BTH 65536u
#define OFF_BTL 81920u
#define OFF_UTH 98304u
#define OFF_UTL 106496u
#define OFF_UWH 114688u
#define OFF_UWL 122880u
#define OFF_GH  131072u
#define OFF_GL  139264u
#define OFF_SDT 147456u          // float[64]
#define OFF_DTS 147712u          // float[64]
#define OFF_WS  147968u          // float[64]
#define SMEM_SSD1 148480u

__global__ __launch_bounds__(256, 1)
void ssd_chunk_kernel(const float* __restrict__ A_log)
{
    extern __shared__ __align__(1024) char smem[];
    const uint32_t sb = smem_u32(smem);
    const int c = blockIdx.x, b = blockIdx.y, hh = blockIdx.z;
    const int tid = threadIdx.x;
    const int wid = tid >> 5, lane = tid & 31;
    const int wm = wid & 1, wn = wid >> 1;
    const int t0 = c * CLEN;
    const float Ah = -expf(A_log[hh]);

    float* s_sdt = (float*)(smem + OFF_SDT);
    float* s_dt  = (float*)(smem + OFF_DTS);
    float* s_w   = (float*)(smem + OFF_WS);

    // ---- dt load + inclusive scan (Hillis-Steele over 64) ----
    if (tid < 64) {
        float d = g_dt[((size_t)b * SEQLEN + t0 + tid) * NHEADS + hh];
        s_dt[tid] = d;
        s_sdt[tid] = d;
    }
    __syncthreads();
#pragma unroll
    for (int off = 1; off < 64; off <<= 1) {
        float v = 0.f;
        if (tid < 64 && tid >= off) v = s_sdt[tid - off];
        __syncthreads();
        if (tid < 64) s_sdt[tid] += v;
        __syncthreads();
    }
    float sdtTOT = s_sdt[63];
    if (tid < 64) s_w[tid] = expf(Ah * (sdtTOT - s_sdt[tid]));
    if (tid == 0) g_pi[((size_t)b * NHEADS + hh) * NCH + c] = sdtTOT;

    // ---- convert C, B (t-major panels; B also n-major transposed) ----
#pragma unroll
    for (int i = 0; i < 8; i++) {
        int idx = tid + i * 256;                 // 2048 float4
        int t = idx >> 5, n4 = idx & 31;
        size_t row = ((size_t)b * SEQLEN + t0 + t) * CONVDIM;
        int kp = n4 >> 4, cb = n4 & 15;
        uint32_t off = (uint32_t)kp * 8192u + (uint32_t)t * 128u
                     + ((((uint32_t)cb >> 1) ^ (t & 7)) << 4) + (cb & 1) * 8;
        // C
        {
            float4 v = *(const float4*)&g_xbc[row + DINNER + DSTATE + n4 * 4];
            __nv_bfloat16 h0,l0,h1,l1,h2,l2,h3,l3;
            hilo(v.x,h0,l0); hilo(v.y,h1,l1); hilo(v.z,h2,l2); hilo(v.w,h3,l3);
            *(__nv_bfloat162*)(smem + OFF_CPH + off)     = __halves2bfloat162(h0,h1);
            *(__nv_bfloat162*)(smem + OFF_CPH + off + 4) = __halves2bfloat162(h2,h3);
            *(__nv_bfloat162*)(smem + OFF_CPL + off)     = __halves2bfloat162(l0,l1);
            *(__nv_bfloat162*)(smem + OFF_CPL + off + 4) = __halves2bfloat162(l2,l3);
        }
        // B (both layouts)
        {
            float4 v = *(const float4*)&g_xbc[row + DINNER + n4 * 4];
            __nv_bfloat16 h[4], l[4];
            hilo(v.x,h[0],l[0]); hilo(v.y,h[1],l[1]); hilo(v.z,h[2],l[2]); hilo(v.w,h[3],l[3]);
            *(__nv_bfloat162*)(smem + OFF_BPH + off)     = __halves2bfloat162(h[0],h[1]);
            *(__nv_bfloat162*)(smem + OFF_BPH + off + 4) = __halves2bfloat162(h[2],h[3]);
            *(__nv_bfloat162*)(smem + OFF_BPL + off)     = __halves2bfloat162(l[0],l[1]);
            *(__nv_bfloat162*)(smem + OFF_BPL + off + 4) = __halves2bfloat162(l[2],l[3]);
#pragma unroll
            for (int j = 0; j < 4; j++) {
                int n = n4 * 4 + j;
                uint32_t toff = swzb(n, t * 2);
                *(__nv_bfloat16*)(smem + OFF_BTH + toff) = h[j];
                *(__nv_bfloat16*)(smem + OFF_BTL + toff) = l[j];
            }
        }
    }
    // ---- convert U = dt*x (p-major transposed) and Uw = w*U ----
#pragma unroll
    for (int i = 0; i < 4; i++) {
        int idx = tid + i * 256;                 // 1024 float4
        int t = idx >> 4, p4 = idx & 15;
        size_t row = ((size_t)b * SEQLEN + t0 + t) * CONVDIM;
        float4 xv = *(const float4*)&g_xbc[row + hh * HEADDIM + p4 * 4];
        float dtv = s_dt[t], wv = s_w[t];
        float u[4] = { dtv*xv.x, dtv*xv.y, dtv*xv.z, dtv*xv.w };
#pragma unroll
        for (int j = 0; j < 4; j++) {
            int p = p4 * 4 + j;
            uint32_t toff = swzb(p, t * 2);
            __nv_bfloat16 h, l;
            hilo(u[j], h, l);
            *(__nv_bfloat16*)(smem + OFF_UTH + toff) = h;
            *(__nv_bfloat16*)(smem + OFF_UTL + toff) = l;
            hilo(u[j] * wv, h, l);
            *(__nv_bfloat16*)(smem + OFF_UWH + toff) = h;
            *(__nv_bfloat16*)(smem + OFF_UWL + toff) = l;
        }
    }
    __syncthreads();

    const int lgrp = lane >> 3, lr = lane & 7;
    const int a_roff = lr + (lgrp & 1) * 8;
    const int a_koff = lgrp >> 1;
    const int b_roff = lr + (lgrp >> 1) * 8;
    const int b_koff = lgrp & 1;
    const int quad = lane >> 2, qt = lane & 3;

    // ---- GEMM2: G = C @ B^T   [64t x 64s], K=n=128 (2 panels) ----
    {
        float accG[2][2][4];
#pragma unroll
        for (int mi = 0; mi < 2; mi++)
#pragma unroll
            for (int ni = 0; ni < 2; ni++)
#pragma unroll
                for (int q = 0; q < 4; q++) accG[mi][ni][q] = 0.f;

#pragma unroll
        for (int kp = 0; kp < 2; kp++) {
#pragma unroll
            for (int k16 = 0; k16 < 4; k16++) {
                int k2 = k16 * 2;
                uint32_t aH[2][4], aL[2][4], bH[2][2], bL[2][2];
#pragma unroll
                for (int mi = 0; mi < 2; mi++) {
                    int row = wm * 32 + mi * 16 + a_roff;
                    uint32_t ad = kp * 8192u + swz(row, k2 + a_koff);
                    ldsm_x4(aH[mi][0], aH[mi][1], aH[mi][2], aH[mi][3], sb + OFF_CPH + ad);
                    ldsm_x4(aL[mi][0], aL[mi][1], aL[mi][2], aL[mi][3], sb + OFF_CPL + ad);
                }
                {
                    int row = wn * 16 + b_roff;
                    uint32_t bd = kp * 8192u + swz(row, k2 + b_koff);
                    uint32_t r0, r1, r2, r3;
                    ldsm_x4(r0, r1, r2, r3, sb + OFF_BPH + bd);
                    bH[0][0] = r0; bH[0][1] = r1; bH[1][0] = r2; bH[1][1] = r3;
                    ldsm_x4(r0, r1, r2, r3, sb + OFF_BPL + bd);
                    bL[0][0] = r0; bL[0][1] = r1; bL[1][0] = r2; bL[1][1] = r3;
                }
#pragma unroll
                for (int mi = 0; mi < 2; mi++)
#pragma unroll
                    for (int ni = 0; ni < 2; ni++) {
                        mma_bf16(accG[mi][ni], aH[mi], bH[ni][0], bH[ni][1]);
                        mma_bf16(accG[mi][ni], aH[mi], bL[ni][0], bL[ni][1]);
                        mma_bf16(accG[mi][ni], aL[mi], bH[ni][0], bH[ni][1]);
                    }
            }
        }
        // scale/mask and store G (bf16 hi/lo)
#pragma unroll
        for (int mi = 0; mi < 2; mi++)
#pragma unroll
            for (int ni = 0; ni < 2; ni++)
#pragma unroll
                for (int half = 0; half < 2; half++) {
                    int t = wm * 32 + mi * 16 + quad + half * 8;
                    int s = wn * 16 + ni * 8 + qt * 2;
                    float sdt_t = s_sdt[t];
                    float v0 = accG[mi][ni][half * 2 + 0];
                    float v1 = accG[mi][ni][half * 2 + 1];
                    v0 = (t >= s)     ? v0 * expf(Ah * (sdt_t - s_sdt[s]))     : 0.f;
                    v1 = (t >= s + 1) ? v1 * expf(Ah * (sdt_t - s_sdt[s + 1])) : 0.f;
                    __nv_bfloat16 h0,l0,h1,l1;
                    hilo(v0,h0,l0); hilo(v1,h1,l1);
                    uint32_t off = swzb(t, s * 2);
                    *(__nv_bfloat162*)(smem + OFF_GH + off) = __halves2bfloat162(h0,h1);
                    *(__nv_bfloat162*)(smem + OFF_GL + off) = __halves2bfloat162(l0,l1);
                }
    }
    __syncthreads();

    // ---- GEMM4: Y = G @ U  [64t x 64p], K=s=64 ----
    {
        float accY[2][2][4];
#pragma unroll
        for (int mi = 0; mi < 2; mi++)
#pragma unroll
            for (int ni = 0; ni < 2; ni++)
#pragma unroll
                for (int q = 0; q < 4; q++) accY[mi][ni][q] = 0.f;

#pragma unroll
        for (int k16 = 0; k16 < 4; k16++) {
            int k2 = k16 * 2;
            uint32_t aH[2][4], aL[2][4], bH[2][2], bL[2][2];
#pragma unroll
            for (int mi = 0; mi < 2; mi++) {
                int row = wm * 32 + mi * 16 + a_roff;
                uint32_t ad = swz(row, k2 + a_koff);
                ldsm_x4(aH[mi][0], aH[mi][1], aH[mi][2], aH[mi][3], sb + OFF_GH + ad);
                ldsm_x4(aL[mi][0], aL[mi][1], aL[mi][2], aL[mi][3], sb + OFF_GL + ad);
            }
            {
                int row = wn * 16 + b_roff;
                uint32_t bd = swz(row, k2 + b_koff);
                uint32_t r0, r1, r2, r3;
                ldsm_x4(r0, r1, r2, r3, sb + OFF_UTH + bd);
                bH[0][0] = r0; bH[0][1] = r1; bH[1][0] = r2; bH[1][1] = r3;
                ldsm_x4(r0, r1, r2, r3, sb + OFF_UTL + bd);
                bL[0][0] = r0; bL[0][1] = r1; bL[1][0] = r2; bL[1][1] = r3;
            }
#pragma unroll
            for (int mi = 0; mi < 2; mi++)
#pragma unroll
                for (int ni = 0; ni < 2; ni++) {
                    mma_bf16(accY[mi][ni], aH[mi], bH[ni][0], bH[ni][1]);
                    mma_bf16(accY[mi][ni], aH[mi], bL[ni][0], bL[ni][1]);
                    mma_bf16(accY[mi][ni], aL[mi], bH[ni][0], bH[ni][1]);
                }
        }
#pragma unroll
        for (int mi = 0; mi < 2; mi++)
#pragma unroll
            for (int ni = 0; ni < 2; ni++) {
                int t = wm * 32 + mi * 16 + quad;
                int p = wn * 16 + ni * 8 + qt * 2;
                size_t o = ((size_t)b * SEQLEN + t0 + t) * DINNER + hh * HEADDIM + p;
                *(float2*)&g_y[o] = make_float2(accY[mi][ni][0], accY[mi][ni][1]);
                o += (size_t)8 * DINNER;
                *(float2*)&g_y[o] = make_float2(accY[mi][ni][2], accY[mi][ni][3]);
            }
    }

    // ---- GEMM5: Hc = Uw @ Bt^T-form  [64p x 128n], K=s=64 ----
    {
        float accH[2][4][4];
#pragma unroll
        for (int mi = 0; mi < 2; mi++)
#pragma unroll
            for (int ni = 0; ni < 4; ni++)
#pragma unroll
                for (int q = 0; q < 4; q++) accH[mi][ni][q] = 0.f;

#pragma unroll
        for (int k16 = 0; k16 < 4; k16++) {
            int k2 = k16 * 2;
            uint32_t aH[2][4], aL[2][4], bH[4][2], bL[4][2];
#pragma unroll
            for (int mi = 0; mi < 2; mi++) {
                int row = wm * 32 + mi * 16 + a_roff;
                uint32_t ad = swz(row, k2 + a_koff);
                ldsm_x4(aH[mi][0], aH[mi][1], aH[mi][2], aH[mi][3], sb + OFF_UWH + ad);
                ldsm_x4(aL[mi][0], aL[mi][1], aL[mi][2], aL[mi][3], sb + OFF_UWL + ad);
            }
#pragma unroll
            for (int nj = 0; nj < 2; nj++) {
                int row = wn * 32 + nj * 16 + b_roff;
                uint32_t bd = swz(row, k2 + b_koff);
                uint32_t r0, r1, r2, r3;
                ldsm_x4(r0, r1, r2, r3, sb + OFF_BTH + bd);
                bH[nj*2][0] = r0; bH[nj*2][1] = r1; bH[nj*2+1][0] = r2; bH[nj*2+1][1] = r3;
                ldsm_x4(r0, r1, r2, r3, sb + OFF_BTL + bd);
                bL[nj*2][0] = r0; bL[nj*2][1] = r1; bL[nj*2+1][0] = r2; bL[nj*2+1][1] = r3;
            }
#pragma unroll
            for (int mi = 0; mi < 2; mi++)
#pragma unroll
                for (int ni = 0; ni < 4; ni++) {
                    mma_bf16(accH[mi][ni], aH[mi], bH[ni][0], bH[ni][1]);
                    mma_bf16(accH[mi][ni], aH[mi], bL[ni][0], bL[ni][1]);
                    mma_bf16(accH[mi][ni], aL[mi], bH[ni][0], bH[ni][1]);
                }
        }
        float* hc = &g_hc[(((size_t)b * NHEADS + hh) * NCH + c) * (HEADDIM * DSTATE)];
#pragma unroll
        for (int mi = 0; mi < 2; mi++)
#pragma unroll
            for (int ni = 0; ni < 4; ni++) {
                int p = wm * 32 + mi * 16 + quad;
                int n = wn * 32 + ni * 8 + qt * 2;
                *(float2*)&hc[p * DSTATE + n] = make_float2(accH[mi][ni][0], accH[mi][ni][1]);
                *(float2*)&hc[(p + 8) * DSTATE + n] = make_float2(accH[mi][ni][2], accH[mi][ni][3]);
            }
    }
}

// =====================================================================
// SSD phase 2: inter-chunk state recurrence (64 blocks, elementwise)
// h0[c] = exp(A*pi[c-1]) * h0[c-1] + Hc[c-1]
// =====================================================================
__global__ __launch_bounds__(256)
void ssd_prop_kernel(const float* __restrict__ A_log)
{
    const int bh = blockIdx.x;
    const int hh = bh & (NHEADS - 1);
    const int tid = threadIdx.x;
    const float Ah = -expf(A_log[hh]);

    float4 acc[8];
#pragma unroll
    for (int j = 0; j < 8; j++) acc[j] = make_float4(0.f, 0.f, 0.f, 0.f);

    for (int c = 1; c < NCH; c++) {
        float Pi = expf(Ah * g_pi[(size_t)bh * NCH + c - 1]);
        const float4* hc = (const float4*)&g_hc[((size_t)bh * NCH + c - 1) * (HEADDIM * DSTATE)];
        float4* h0 = (float4*)&g_h0[((size_t)bh * NCH + c) * (HEADDIM * DSTATE)];
#pragma unroll
        for (int j = 0; j < 8; j++) {
            float4 v = hc[tid * 8 + j];
            acc[j].x = Pi * acc[j].x + v.x;
            acc[j].y = Pi * acc[j].y + v.y;
            acc[j].z = Pi * acc[j].z + v.z;
            acc[j].w = Pi * acc[j].w + v.w;
            h0[tid * 8 + j] = acc[j];
        }
    }
}

// =====================================================================
// SSD phase 3: carry  Y_t += r_t * (C_t @ h0)   (chunks 1..15)
// grid (NCH-1, BATCH, NHEADS)
// smem: Cp panels 32KB + H0 panels 32KB + scalars
// =====================================================================
#define C3_CPH 0u
#define C3_CPL 16384u
#define C3_H0H 32768u
#define C3_H0L 49152u
#define C3_SDT 65536u
#define C3_R   65792u
#define SMEM_SSD3 66560u

__global__ __launch_bounds__(256)
void ssd_carry_kernel(const float* __restrict__ A_log)
{
    extern __shared__ __align__(1024) char smem[];
    const uint32_t sb = smem_u32(smem);
    const int c = blockIdx.x + 1, b = blockIdx.y, hh = blockIdx.z;
    const int tid = threadIdx.x;
    const int wid = tid >> 5, lane = tid & 31;
    const int wm = wid & 1, wn = wid >> 1;
    const int t0 = c * CLEN;
    const float Ah = -expf(A_log[hh]);

    float* s_sdt = (float*)(smem + C3_SDT);
    float* s_r   = (float*)(smem + C3_R);

    if (tid < 64)
        s_sdt[tid] = g_dt[((size_t)b * SEQLEN + t0 + tid) * NHEADS + hh];
    __syncthreads();
#pragma unroll
    for (int off = 1; off < 64; off <<= 1) {
        float v = 0.f;
        if (tid < 64 && tid >= off) v = s_sdt[tid - off];
        __syncthreads();
        if (tid < 64) s_sdt[tid] += v;
        __syncthreads();
    }
    if (tid < 64) s_r[tid] = expf(Ah * s_sdt[tid]);

    // convert C panels and h0 panels
    const float* h0src = &g_h0[(((size_t)b * NHEADS + hh) * NCH + c) * (HEADDIM * DSTATE)];
#pragma unroll
    for (int i = 0; i < 8; i++) {
        int idx = tid + i * 256;
        int r = idx >> 5, n4 = idx & 31;
        int kp = n4 >> 4, cb = n4 & 15;
        uint32_t off = (uint32_t)kp * 8192u + (uint32_t)r * 128u
                     + ((((uint32_t)cb >> 1) ^ (r & 7)) << 4) + (cb & 1) * 8;
        {
            size_t row = ((size_t)b * SEQLEN + t0 + r) * CONVDIM;
            float4 v = *(const float4*)&g_xbc[row + DINNER + DSTATE + n4 * 4];
            __nv_bfloat16 h0b,l0,h1,l1,h2,l2,h3,l3;
            hilo(v.x,h0b,l0); hilo(v.y,h1,l1); hilo(v.z,h2,l2); hilo(v.w,h3,l3);
            *(__nv_bfloat162*)(smem + C3_CPH + off)     = __halves2bfloat162(h0b,h1);
            *(__nv_bfloat162*)(smem + C3_CPH + off + 4) = __halves2bfloat162(h2,h3);
            *(__nv_bfloat162*)(smem + C3_CPL + off)     = __halves2bfloat162(l0,l1);
            *(__nv_bfloat162*)(smem + C3_CPL + off + 4) = __halves2bfloat162(l2,l3);
        }
        {
            float4 v = *(const float4*)&h0src[r * DSTATE + n4 * 4];
            __nv_bfloat16 h0b,l0,h1,l1,h2,l2,h3,l3;
            hilo(v.x,h0b,l0); hilo(v.y,h1,l1); hilo(v.z,h2,l2); hilo(v.w,h3,l3);
            *(__nv_bfloat162*)(smem + C3_H0H + off)     = __halves2bfloat162(h0b,h1);
            *(__nv_bfloat162*)(smem + C3_H0H + off + 4) = __halves2bfloat162(h2,h3);
            *(__nv_bfloat162*)(smem + C3_H0L + off)     = __halves2bfloat162(l0,l1);
            *(__nv_bfloat162*)(smem + C3_H0L + off + 4) = __halves2bfloat162(l2,l3);
        }
    }
    __syncthreads();

    const int lgrp = lane >> 3, lr = lane & 7;
    const int a_roff = lr + (lgrp & 1) * 8;
    const int a_koff = lgrp >> 1;
    const int b_roff = lr + (lgrp >> 1) * 8;
    const int b_koff = lgrp & 1;
    const int quad = lane >> 2, qt = lane & 3;

    float acc[2][2][4];
#pragma unroll
    for (int mi = 0; mi < 2; mi++)
#pragma unroll
        for (int ni = 0; ni < 2; ni++)
#pragma unroll
            for (int q = 0; q < 4; q++) acc[mi][ni][q] = 0.f;

#pragma unroll
    for (int kp = 0; kp < 2; kp++) {
#pragma unroll
        for (int k16 = 0; k16 < 4; k16++) {
            int k2 = k16 * 2;
            uint32_t aH[2][4], aL[2][4], bH[2][2], bL[2][2];
#pragma unroll
            for (int mi = 0; mi < 2; mi++) {
                int row = wm * 32 + mi * 16 + a_roff;
                uint32_t ad = kp * 8192u + swz(row, k2 + a_koff);
                ldsm_x4(aH[mi][0], aH[mi][1], aH[mi][2], aH[mi][3], sb + C3_CPH + ad);
                ldsm_x4(aL[mi][0], aL[mi][1], aL[mi][2], aL[mi][3], sb + C3_CPL + ad);
            }
            {
                int row = wn * 16 + b_roff;
                uint32_t bd = kp * 8192u + swz(row, k2 + b_koff);
                uint32_t r0, r1, r2, r3;
                ldsm_x4(r0, r1, r2, r3, sb + C3_H0H + bd);
                bH[0][0] = r0; bH[0][1] = r1; bH[1][0] = r2; bH[1][1] = r3;
                ldsm_x4(r0, r1, r2, r3, sb + C3_H0L + bd);
                bL[0][0] = r0; bL[0][1] = r1; bL[1][0] = r2; bL[1][1] = r3;
            }
#pragma unroll
            for (int mi = 0; mi < 2; mi++)
#pragma unroll
                for (int ni = 0; ni < 2; ni++) {
                    mma_bf16(acc[mi][ni], aH[mi], bH[ni][0], bH[ni][1]);
                    mma_bf16(acc[mi][ni], aH[mi], bL[ni][0], bL[ni][1]);
                    mma_bf16(acc[mi][ni], aL[mi], bH[ni][0], bH[ni][1]);
                }
        }
    }

#pragma unroll
    for (int mi = 0; mi < 2; mi++)
#pragma unroll
        for (int ni = 0; ni < 2; ni++) {
            int t = wm * 32 + mi * 16 + quad;
            int p = wn * 16 + ni * 8 + qt * 2;
            {
                float rt = s_r[t];
                size_t o = ((size_t)b * SEQLEN + t0 + t) * DINNER + hh * HEADDIM + p;
                float2 v = *(float2*)&g_y[o];
                v.x += rt * acc[mi][ni][0];
                v.y += rt * acc[mi][ni][1];
                *(float2*)&g_y[o] = v;
            }
            {
                float rt = s_r[t + 8];
                size_t o = ((size_t)b * SEQLEN + t0 + t + 8) * DINNER + hh * HEADDIM + p;
                float2 v = *(float2*)&g_y[o];
                v.x += rt * acc[mi][ni][2];
                v.y += rt * acc[mi][ni][3];
                *(float2*)&g_y[o] = v;
            }
        }
}

// =====================================================================
// skip + gate + RMSNorm -> bf16 hi/lo
// =====================================================================
__global__ __launch_bounds__(256)
void gate_norm_kernel(const float* __restrict__ Dw, const float* __restrict__ norm_w)
{
    const int t = blockIdx.x;
    const int b = blockIdx.y;
    const size_t row = (size_t)b * SEQLEN + t;
    const float4* __restrict__ z4 = (const float4*)&g_zx [row * DINPROJ];
    const float4* __restrict__ x4 = (const float4*)&g_xbc[row * CONVDIM];
    const float4* __restrict__ y4 = (const float4*)&g_y  [row * DINNER];

    float4 vals[2];
    float ss = 0.f;
#pragma unroll
    for (int r = 0; r < 2; r++) {
        int f = r * 256 + threadIdx.x;
        float dv = Dw[f >> 4];
        float4 a = y4[f], xv = x4[f], zv = z4[f];
        float4 v;
        v.x = a.x + dv * xv.x;
        v.y = a.y + dv * xv.y;
        v.z = a.z + dv * xv.z;
        v.w = a.w + dv * xv.w;
        v.x *= zv.x / (1.f + expf(-zv.x));
        v.y *= zv.y / (1.f + expf(-zv.y));
        v.z *= zv.z / (1.f + expf(-zv.z));
        v.w *= zv.w / (1.f + expf(-zv.w));
        vals[r] = v;
        ss += v.x * v.x + v.y * v.y + v.z * v.z + v.w * v.w;
    }
    __shared__ float red[256];
    red[threadIdx.x] = ss;
    __syncthreads();
    for (int off = 128; off > 0; off >>= 1) {
        if (threadIdx.x < off) red[threadIdx.x] += red[threadIdx.x + off];
        __syncthreads();
    }
    float scale = rsqrtf(red[0] / (float)DINNER + EPS);
    __nv_bfloat162* outh = (__nv_bfloat162*)&g_ynh[row * DINNER];
    __nv_bfloat162* outl = (__nv_bfloat162*)&g_ynl[row * DINNER];
    const float4* nw4 = (const float4*)norm_w;
#pragma unroll
    for (int r = 0; r < 2; r++) {
        int f = r * 256 + threadIdx.x;
        float4 w = nw4[f];
        float4 v = vals[r];
        v.x *= scale * w.x; v.y *= scale * w.y; v.z *= scale * w.z; v.w *= scale * w.w;
        split4(v, outh, outl, f);
    }
}

// =====================================================================
extern "C" void kernel_launch(void* const* d_in, const int* in_sizes, int n_in,
                              void* d_out, int out_size)
{
    const float* x          = (const float*)d_in[0];
    const float* in_proj_w  = (const float*)d_in[1];
    const float* conv_w     = (const float*)d_in[2];
    const float* conv_b     = (const float*)d_in[3];
    const float* dt_bias    = (const float*)d_in[4];
    const float* A_log      = (const float*)d_in[5];
    const float* Dw         = (const float*)d_in[6];
    const float* norm_w     = (const float*)d_in[7];
    const float* out_proj_w = (const float*)d_in[8];
    float* out = (float*)d_out;

    float *p_zx = nullptr;
    void *p_xh, *p_xl, *p_w1h, *p_w1l, *p_w2h, *p_w2l, *p_ynh, *p_ynl;
    cudaGetSymbolAddress((void**)&p_zx, g_zx);
    cudaGetSymbolAddress(&p_xh,  g_xh);  cudaGetSymbolAddress(&p_xl,  g_xl);
    cudaGetSymbolAddress(&p_w1h, g_w1h); cudaGetSymbolAddress(&p_w1l, g_w1l);
    cudaGetSymbolAddress(&p_w2h, g_w2h); cudaGetSymbolAddress(&p_w2l, g_w2l);
    cudaGetSymbolAddress(&p_ynh, g_ynh); cudaGetSymbolAddress(&p_ynl, g_ynl);

    cudaFuncSetAttribute(gemm_mma<false>, cudaFuncAttributeMaxDynamicSharedMemorySize, SMEM_GEMM);
    cudaFuncSetAttribute(gemm_mma<true>,  cudaFuncAttributeMaxDynamicSharedMemorySize, SMEM_GEMM);
    cudaFuncSetAttribute(ssd_chunk_kernel, cudaFuncAttributeMaxDynamicSharedMemorySize, SMEM_SSD1);
    cudaFuncSetAttribute(ssd_carry_kernel, cudaFuncAttributeMaxDynamicSharedMemorySize, SMEM_SSD3);

    // 0) fp32 -> bf16 hi/lo conversions
    {
        int total4 = N4_X + N4_W1 + N4_W2;
        cvt_all<<<(total4 + 255)/256, 256>>>(
            (const float4*)x, (const float4*)in_proj_w, (const float4*)out_proj_w);
    }

    // 1) zxbcdt = x @ in_proj_w^T
    gemm_mma<false><<<dim3((DINPROJ + BN - 1)/BN, ROWS/BM), 256, SMEM_GEMM>>>(
        (const __nv_bfloat16*)p_xh, (const __nv_bfloat16*)p_xl,
        (const __nv_bfloat16*)p_w1h, (const __nv_bfloat16*)p_w1l,
        nullptr, p_zx, DINPROJ, DMODEL);

    // 2) conv + SiLU; dt softplus
    conv_act_kernel<<<dim3(CONVDIM/256, SEQLEN/4, BATCH), 256>>>(conv_w, conv_b, dt_bias);

    // 3) SSD scan: chunk-local (tensor cores) -> state recurrence -> carry
    ssd_chunk_kernel<<<dim3(NCH, BATCH, NHEADS), 256, SMEM_SSD1>>>(A_log);
    ssd_prop_kernel<<<BATCH * NHEADS, 256>>>(A_log);
    ssd_carry_kernel<<<dim3(NCH - 1, BATCH, NHEADS), 256, SMEM_SSD3>>>(A_log);

    // 4) skip + gate + RMSNorm
    gate_norm_kernel<<<dim3(SEQLEN, BATCH), 256>>>(Dw, norm_w);

    // 5) out = x + yn @ out_proj_w^T
    gemm_mma<true><<<dim3(DMODEL/BN, ROWS/BM), 256, SMEM_GEMM>>>(
        (const __nv_bfloat16*)p_ynh, (const __nv_bfloat16*)p_ynl,
        (const __nv_bfloat16*)p_w2h, (const __nv_bfloat16*)p_w2l,
        x, out, DMODEL, DINNER);
}

// round 8
// speedup vs baseline: 1.5740x; 1.1355x over previous
#include <cuda_runtime.h>
#include <cuda_bf16.h>
#include <math.h>
#include <stdint.h>

// ---------------- problem constants ----------------
#define BATCH    2
#define SEQLEN   1024
#define DMODEL   1024
#define DINNER   2048
#define NHEADS   32
#define HEADDIM  64
#define DSTATE   128
#define DCONV    4
#define CONVDIM  2304
#define DINPROJ  4384
#define ROWS     (BATCH*SEQLEN)
#define EPS      1e-5f
#define CLEN     64
#define NCH      (SEQLEN/CLEN)     // 16 chunks

// ---------------- scratch ----------------
__device__ __align__(1024) float g_zx [ROWS*DINPROJ];
__device__ __align__(1024) float g_xbc[ROWS*CONVDIM];
__device__ __align__(1024) float g_dt [ROWS*NHEADS];
__device__ __align__(1024) float g_y  [ROWS*DINNER];
__device__ __align__(1024) float g_hc [BATCH*NHEADS*NCH*HEADDIM*DSTATE];
__device__ __align__(1024) float g_h0 [BATCH*NHEADS*NCH*HEADDIM*DSTATE];
__device__ __align__(1024) float g_pi [BATCH*NHEADS*NCH];
__device__ __align__(1024) __nv_bfloat16 g_xh [ROWS*DMODEL];
__device__ __align__(1024) __nv_bfloat16 g_xl [ROWS*DMODEL];
__device__ __align__(1024) __nv_bfloat16 g_w1h[DINPROJ*DMODEL];
__device__ __align__(1024) __nv_bfloat16 g_w1l[DINPROJ*DMODEL];
__device__ __align__(1024) __nv_bfloat16 g_w2h[DMODEL*DINNER];
__device__ __align__(1024) __nv_bfloat16 g_w2l[DMODEL*DINNER];
__device__ __align__(1024) __nv_bfloat16 g_ynh[ROWS*DINNER];
__device__ __align__(1024) __nv_bfloat16 g_ynl[ROWS*DINNER];

// ---------------- primitives ----------------
__device__ __forceinline__ uint32_t smem_u32(const void* p) {
    uint32_t a;
    asm("{ .reg .u64 t; cvta.to.shared.u64 t, %1; cvt.u32.u64 %0, t; }" : "=r"(a) : "l"(p));
    return a;
}
__device__ __forceinline__ void cp16(uint32_t dst, const void* src) {
    asm volatile("cp.async.cg.shared.global [%0], [%1], 16;" :: "r"(dst), "l"(src));
}
__device__ __forceinline__ void cp_commit() { asm volatile("cp.async.commit_group;" ::: "memory"); }
template<int W> __device__ __forceinline__ void cp_wait() {
    asm volatile("cp.async.wait_group %0;" :: "n"(W) : "memory");
}
__device__ __forceinline__ void ldsm_x4(uint32_t& r0, uint32_t& r1, uint32_t& r2, uint32_t& r3, uint32_t a) {
    asm volatile("ldmatrix.sync.aligned.m8n8.x4.shared.b16 {%0,%1,%2,%3}, [%4];"
                 : "=r"(r0), "=r"(r1), "=r"(r2), "=r"(r3) : "r"(a));
}
__device__ __forceinline__ void ldsm_x4_t(uint32_t& r0, uint32_t& r1, uint32_t& r2, uint32_t& r3, uint32_t a) {
    asm volatile("ldmatrix.sync.aligned.m8n8.x4.trans.shared.b16 {%0,%1,%2,%3}, [%4];"
                 : "=r"(r0), "=r"(r1), "=r"(r2), "=r"(r3) : "r"(a));
}
__device__ __forceinline__ void mma_bf16(float* c, const uint32_t* a, uint32_t b0, uint32_t b1) {
    asm volatile(
        "mma.sync.aligned.m16n8k16.row.col.f32.bf16.bf16.f32 "
        "{%0,%1,%2,%3}, {%4,%5,%6,%7}, {%8,%9}, {%0,%1,%2,%3};"
        : "+f"(c[0]), "+f"(c[1]), "+f"(c[2]), "+f"(c[3])
        : "r"(a[0]), "r"(a[1]), "r"(a[2]), "r"(a[3]), "r"(b0), "r"(b1));
}
__device__ __forceinline__ uint32_t swz(int row, int seg) {
    return (uint32_t)(row * 128 + ((seg ^ (row & 7)) << 4));
}
__device__ __forceinline__ uint32_t swzb(int row, int colb) {
    return (uint32_t)(row * 128 + (((colb >> 4) ^ (row & 7)) << 4) + (colb & 15));
}
__device__ __forceinline__ void hilo(float v, __nv_bfloat16& h, __nv_bfloat16& l) {
    h = __float2bfloat16(v);
    l = __float2bfloat16(v - __bfloat162float(h));
}

// =====================================================================
// Tensor-core GEMM (verified; unchanged)
// =====================================================================
#define BM 128
#define BN 128
#define KC 64
#define TILE_B   16384u
#define STAGE_B  (4u*TILE_B)
#define NSTAGE   3
#define SMEM_GEMM (NSTAGE*STAGE_B)

template<bool RES>
__global__ __launch_bounds__(256, 1)
void gemm_mma(const __nv_bfloat16* __restrict__ Ahp, const __nv_bfloat16* __restrict__ Alp,
              const __nv_bfloat16* __restrict__ Bhp, const __nv_bfloat16* __restrict__ Blp,
              const float* __restrict__ resid, float* __restrict__ C,
              int N, int K)
{
    extern __shared__ __align__(1024) char smem[];
    const uint32_t sb = smem_u32(smem);

    const int tid = threadIdx.x;
    const int wid = tid >> 5, lane = tid & 31;
    const int wm = wid & 1, wn = wid >> 1;
    const int m0 = blockIdx.y * BM, n0 = blockIdx.x * BN;
    const int NC = K / KC;

    int lrow[4], lseg[4];
#pragma unroll
    for (int it = 0; it < 4; it++) {
        int idx = tid + it * 256;
        lrow[it] = idx >> 3;
        lseg[it] = idx & 7;
    }

    auto load_chunk = [&](int stage, int k0) {
        uint32_t s = sb + stage * STAGE_B;
#pragma unroll
        for (int it = 0; it < 4; it++) {
            int row = lrow[it], seg = lseg[it];
            uint32_t d = swz(row, seg);
            size_t aoff = (size_t)(m0 + row) * K + k0 + seg * 8;
            cp16(s + d,              Ahp + aoff);
            cp16(s + TILE_B + d,     Alp + aoff);
            int brow = n0 + row; if (brow >= N) brow = N - 1;
            size_t boff = (size_t)brow * K + k0 + seg * 8;
            cp16(s + 2 * TILE_B + d, Bhp + boff);
            cp16(s + 3 * TILE_B + d, Blp + boff);
        }
        cp_commit();
    };

    float acc[4][4][4];
#pragma unroll
    for (int mi = 0; mi < 4; mi++)
#pragma unroll
        for (int ni = 0; ni < 4; ni++)
#pragma unroll
            for (int q = 0; q < 4; q++) acc[mi][ni][q] = 0.f;

    const int lgrp = lane >> 3, lr = lane & 7;
    const int a_roff = lr + (lgrp & 1) * 8;
    const int a_koff = lgrp >> 1;
    const int b_roff = lr + (lgrp >> 1) * 8;
    const int b_koff = lgrp & 1;

    load_chunk(0, 0);
    load_chunk(1, KC);

    for (int c = 0; c < NC; c++) {
        if (c + 2 < NC) load_chunk((c + 2) % NSTAGE, (c + 2) * KC);
        else            cp_commit();
        cp_wait<2>();
        __syncthreads();

        uint32_t s = sb + (c % NSTAGE) * STAGE_B;
#pragma unroll
        for (int k16 = 0; k16 < 4; k16++) {
            int k2 = k16 * 2;
            uint32_t ah[4][4], al[4][4], bh[4][2], bl[4][2];
#pragma unroll
            for (int mi = 0; mi < 4; mi++) {
                int row = wm * 64 + mi * 16 + a_roff;
                uint32_t ad = swz(row, k2 + a_koff);
                ldsm_x4(ah[mi][0], ah[mi][1], ah[mi][2], ah[mi][3], s + ad);
                ldsm_x4(al[mi][0], al[mi][1], al[mi][2], al[mi][3], s + TILE_B + ad);
            }
#pragma unroll
            for (int nj = 0; nj < 2; nj++) {
                int row = wn * 32 + nj * 16 + b_roff;
                uint32_t bd = swz(row, k2 + b_koff);
                uint32_t r0, r1, r2, r3;
                ldsm_x4(r0, r1, r2, r3, s + 2 * TILE_B + bd);
                bh[nj * 2][0] = r0; bh[nj * 2][1] = r1;
                bh[nj * 2 + 1][0] = r2; bh[nj * 2 + 1][1] = r3;
                ldsm_x4(r0, r1, r2, r3, s + 3 * TILE_B + bd);
                bl[nj * 2][0] = r0; bl[nj * 2][1] = r1;
                bl[nj * 2 + 1][0] = r2; bl[nj * 2 + 1][1] = r3;
            }
#pragma unroll
            for (int mi = 0; mi < 4; mi++)
#pragma unroll
                for (int ni = 0; ni < 4; ni++) {
                    mma_bf16(acc[mi][ni], ah[mi], bh[ni][0], bh[ni][1]);
                    mma_bf16(acc[mi][ni], ah[mi], bl[ni][0], bl[ni][1]);
                    mma_bf16(acc[mi][ni], al[mi], bh[ni][0], bh[ni][1]);
                }
        }
        __syncthreads();
    }

    const int quad = lane >> 2, qt = lane & 3;
#pragma unroll
    for (int mi = 0; mi < 4; mi++) {
#pragma unroll
        for (int ni = 0; ni < 4; ni++) {
            int gm = m0 + wm * 64 + mi * 16 + quad;
            int gn = n0 + wn * 32 + ni * 8 + qt * 2;
            if (gn < N) {
                {
                    float2 v = make_float2(acc[mi][ni][0], acc[mi][ni][1]);
                    size_t o = (size_t)gm * N + gn;
                    if (RES) { float2 rv = *(const float2*)(resid + o); v.x += rv.x; v.y += rv.y; }
                    *(float2*)(C + o) = v;
                }
                {
                    float2 v = make_float2(acc[mi][ni][2], acc[mi][ni][3]);
                    size_t o = (size_t)(gm + 8) * N + gn;
                    if (RES) { float2 rv = *(const float2*)(resid + o); v.x += rv.x; v.y += rv.y; }
                    *(float2*)(C + o) = v;
                }
            }
        }
    }
}

// =====================================================================
// merged fp32 -> bf16 hi/lo split
// =====================================================================
#define N4_X  (ROWS*DMODEL/4)
#define N4_W1 (DINPROJ*DMODEL/4)
#define N4_W2 (DMODEL*DINNER/4)

__device__ __forceinline__ void split4(float4 v, __nv_bfloat162* hi, __nv_bfloat162* lo, int i) {
    __nv_bfloat16 hx, lx, hy, ly, hz, lz, hw, lw;
    hilo(v.x, hx, lx); hilo(v.y, hy, ly); hilo(v.z, hz, lz); hilo(v.w, hw, lw);
    hi[i * 2]     = __halves2bfloat162(hx, hy);
    hi[i * 2 + 1] = __halves2bfloat162(hz, hw);
    lo[i * 2]     = __halves2bfloat162(lx, ly);
    lo[i * 2 + 1] = __halves2bfloat162(lz, lw);
}

__global__ __launch_bounds__(256)
void cvt_all(const float4* __restrict__ x, const float4* __restrict__ w1,
             const float4* __restrict__ w2)
{
    int i = blockIdx.x * 256 + threadIdx.x;
    if (i < N4_X) {
        split4(x[i], (__nv_bfloat162*)g_xh, (__nv_bfloat162*)g_xl, i);
    } else if (i < N4_X + N4_W1) {
        int j = i - N4_X;
        split4(w1[j], (__nv_bfloat162*)g_w1h, (__nv_bfloat162*)g_w1l, j);
    } else if (i < N4_X + N4_W1 + N4_W2) {
        int j = i - N4_X - N4_W1;
        split4(w2[j], (__nv_bfloat162*)g_w2h, (__nv_bfloat162*)g_w2l, j);
    }
}

// =====================================================================
// Causal depthwise conv + SiLU; dt softplus
// =====================================================================
__global__ __launch_bounds__(256)
void conv_act_kernel(const float* __restrict__ conv_w, const float* __restrict__ conv_b,
                     const float* __restrict__ dt_bias)
{
    const int c  = blockIdx.x * 256 + threadIdx.x;
    const int tb = blockIdx.y * 4;
    const int b  = blockIdx.z;

    float w0 = conv_w[c * 4 + 0], w1 = conv_w[c * 4 + 1];
    float w2 = conv_w[c * 4 + 2], w3 = conv_w[c * 4 + 3];
    float bias = conv_b[c];

    float v[7];
#pragma unroll
    for (int k = 0; k < 7; k++) {
        int tt = tb - 3 + k;
        v[k] = (tt >= 0) ? g_zx[((size_t)b * SEQLEN + tt) * DINPROJ + DINNER + c] : 0.f;
    }
#pragma unroll
    for (int i = 0; i < 4; i++) {
        float a = bias + v[i] * w0 + v[i + 1] * w1 + v[i + 2] * w2 + v[i + 3] * w3;
        g_xbc[((size_t)b * SEQLEN + tb + i) * CONVDIM + c] = a / (1.f + expf(-a));
    }
    if (blockIdx.x == 0 && threadIdx.x < NHEADS) {
        int hh = threadIdx.x;
        float bth = dt_bias[hh];
#pragma unroll
        for (int i = 0; i < 4; i++) {
            size_t row = (size_t)b * SEQLEN + tb + i;
            float raw = g_zx[row * DINPROJ + (DINNER + CONVDIM) + hh] + bth;
            g_dt[row * NHEADS + hh] = (raw > 20.f) ? raw : log1pf(expf(raw));
        }
    }
}

// =====================================================================
// SSD phase 1: per-chunk local scan on tensor cores.
// All operands stored in NATURAL layouts (vectorized writes only);
// transposed operands obtained via ldmatrix.trans:
//   Cp[2][64t][64n], Bp[2][64s][64n]  (B serves GEMM2 normal + GEMM5 trans)
//   Ut[64s][64p], Uw[64s][64p]        (trans for GEMM4-B / GEMM5-A)
//   G [64t][64s]
// =====================================================================
#define OFF_CPH 0u
#define OFF_CPL 16384u
#define OFF_BPH 32768u
#define OFF_BPL 49152u
#define OFF_UTH 65536u
#define OFF_UTL 73728u
#define OFF_UWH 81920u
#define OFF_UWL 90112u
#define OFF_GH  98304u
#define OFF_GL  106496u
#define OFF_SDT 114688u
#define OFF_DTS 114944u
#define OFF_WS  115200u
#define SMEM_SSD1 115456u

__global__ __launch_bounds__(256, 2)
void ssd_chunk_kernel(const float* __restrict__ A_log)
{
    extern __shared__ __align__(1024) char smem[];
    const uint32_t sb = smem_u32(smem);
    const int c = blockIdx.x, b = blockIdx.y, hh = blockIdx.z;
    const int tid = threadIdx.x;
    const int wid = tid >> 5, lane = tid & 31;
    const int wm = wid & 1, wn = wid >> 1;
    const int t0 = c * CLEN;
    const float Ah = -expf(A_log[hh]);

    float* s_sdt = (float*)(smem + OFF_SDT);
    float* s_dt  = (float*)(smem + OFF_DTS);
    float* s_w   = (float*)(smem + OFF_WS);

    // ---- dt load + inclusive scan ----
    if (tid < 64) {
        float d = g_dt[((size_t)b * SEQLEN + t0 + tid) * NHEADS + hh];
        s_dt[tid] = d;
        s_sdt[tid] = d;
    }
    __syncthreads();
#pragma unroll
    for (int off = 1; off < 64; off <<= 1) {
        float v = 0.f;
        if (tid < 64 && tid >= off) v = s_sdt[tid - off];
        __syncthreads();
        if (tid < 64) s_sdt[tid] += v;
        __syncthreads();
    }
    float sdtTOT = s_sdt[63];
    if (tid < 64) s_w[tid] = expf(Ah * (sdtTOT - s_sdt[tid]));
    if (tid == 0) g_pi[((size_t)b * NHEADS + hh) * NCH + c] = sdtTOT;
    __syncthreads();

    // ---- convert C, B (t-major panels; vectorized only) ----
#pragma unroll
    for (int i = 0; i < 8; i++) {
        int idx = tid + i * 256;                 // 2048 float4
        int t = idx >> 5, n4 = idx & 31;
        size_t row = ((size_t)b * SEQLEN + t0 + t) * CONVDIM;
        int kp = n4 >> 4, cb = n4 & 15;
        uint32_t off = (uint32_t)kp * 8192u + (uint32_t)t * 128u
                     + ((((uint32_t)cb >> 1) ^ (t & 7)) << 4) + (cb & 1) * 8;
        {
            float4 v = *(const float4*)&g_xbc[row + DINNER + DSTATE + n4 * 4];
            __nv_bfloat16 h0,l0,h1,l1,h2,l2,h3,l3;
            hilo(v.x,h0,l0); hilo(v.y,h1,l1); hilo(v.z,h2,l2); hilo(v.w,h3,l3);
            *(__nv_bfloat162*)(smem + OFF_CPH + off)     = __halves2bfloat162(h0,h1);
            *(__nv_bfloat162*)(smem + OFF_CPH + off + 4) = __halves2bfloat162(h2,h3);
            *(__nv_bfloat162*)(smem + OFF_CPL + off)     = __halves2bfloat162(l0,l1);
            *(__nv_bfloat162*)(smem + OFF_CPL + off + 4) = __halves2bfloat162(l2,l3);
        }
        {
            float4 v = *(const float4*)&g_xbc[row + DINNER + n4 * 4];
            __nv_bfloat16 h0,l0,h1,l1,h2,l2,h3,l3;
            hilo(v.x,h0,l0); hilo(v.y,h1,l1); hilo(v.z,h2,l2); hilo(v.w,h3,l3);
            *(__nv_bfloat162*)(smem + OFF_BPH + off)     = __halves2bfloat162(h0,h1);
            *(__nv_bfloat162*)(smem + OFF_BPH + off + 4) = __halves2bfloat162(h2,h3);
            *(__nv_bfloat162*)(smem + OFF_BPL + off)     = __halves2bfloat162(l0,l1);
            *(__nv_bfloat162*)(smem + OFF_BPL + off + 4) = __halves2bfloat162(l2,l3);
        }
    }
    // ---- convert U = dt*x and Uw = w*U (natural [s][p] layout, vectorized) ----
#pragma unroll
    for (int i = 0; i < 4; i++) {
        int idx = tid + i * 256;                 // 1024 float4
        int t = idx >> 4, p4 = idx & 15;
        size_t row = ((size_t)b * SEQLEN + t0 + t) * CONVDIM;
        float4 xv = *(const float4*)&g_xbc[row + hh * HEADDIM + p4 * 4];
        float dtv = s_dt[t], wv = s_w[t];
        float u0 = dtv*xv.x, u1 = dtv*xv.y, u2 = dtv*xv.z, u3 = dtv*xv.w;
        uint32_t off = swzb(t, p4 * 8);
        __nv_bfloat16 h0,l0,h1,l1,h2,l2,h3,l3;
        hilo(u0,h0,l0); hilo(u1,h1,l1); hilo(u2,h2,l2); hilo(u3,h3,l3);
        *(__nv_bfloat162*)(smem + OFF_UTH + off)     = __halves2bfloat162(h0,h1);
        *(__nv_bfloat162*)(smem + OFF_UTH + off + 4) = __halves2bfloat162(h2,h3);
        *(__nv_bfloat162*)(smem + OFF_UTL + off)     = __halves2bfloat162(l0,l1);
        *(__nv_bfloat162*)(smem + OFF_UTL + off + 4) = __halves2bfloat162(l2,l3);
        hilo(u0*wv,h0,l0); hilo(u1*wv,h1,l1); hilo(u2*wv,h2,l2); hilo(u3*wv,h3,l3);
        *(__nv_bfloat162*)(smem + OFF_UWH + off)     = __halves2bfloat162(h0,h1);
        *(__nv_bfloat162*)(smem + OFF_UWH + off + 4) = __halves2bfloat162(h2,h3);
        *(__nv_bfloat162*)(smem + OFF_UWL + off)     = __halves2bfloat162(l0,l1);
        *(__nv_bfloat162*)(smem + OFF_UWL + off + 4) = __halves2bfloat162(l2,l3);
    }
    __syncthreads();

    const int lgrp = lane >> 3, lr = lane & 7;
    const int a_roff = lr + (lgrp & 1) * 8;
    const int a_koff = lgrp >> 1;
    const int b_roff = lr + (lgrp >> 1) * 8;
    const int b_koff = lgrp & 1;
    const int quad = lane >> 2, qt = lane & 3;
    // trans-ldmatrix address components
    const int bt_row = lr + (lgrp & 1) * 8;          // B-operand trans
    const int bt_col = (lgrp >> 1) * 8;
    const int at_row = lr + (lgrp >> 1) * 8;         // A-operand trans
    const int at_col = (lgrp & 1) * 8;

    // ---- GEMM2: G = C @ B^T   [64t x 64s], K=n=128 ----
    {
        float accG[2][2][4];
#pragma unroll
        for (int mi = 0; mi < 2; mi++)
#pragma unroll
            for (int ni = 0; ni < 2; ni++)
#pragma unroll
                for (int q = 0; q < 4; q++) accG[mi][ni][q] = 0.f;

#pragma unroll
        for (int kp = 0; kp < 2; kp++) {
#pragma unroll
            for (int k16 = 0; k16 < 4; k16++) {
                int k2 = k16 * 2;
                uint32_t aH[2][4], aL[2][4], bH[2][2], bL[2][2];
#pragma unroll
                for (int mi = 0; mi < 2; mi++) {
                    int row = wm * 32 + mi * 16 + a_roff;
                    uint32_t ad = kp * 8192u + swz(row, k2 + a_koff);
                    ldsm_x4(aH[mi][0], aH[mi][1], aH[mi][2], aH[mi][3], sb + OFF_CPH + ad);
                    ldsm_x4(aL[mi][0], aL[mi][1], aL[mi][2], aL[mi][3], sb + OFF_CPL + ad);
                }
                {
                    int row = wn * 16 + b_roff;
                    uint32_t bd = kp * 8192u + swz(row, k2 + b_koff);
                    uint32_t r0, r1, r2, r3;
                    ldsm_x4(r0, r1, r2, r3, sb + OFF_BPH + bd);
                    bH[0][0] = r0; bH[0][1] = r1; bH[1][0] = r2; bH[1][1] = r3;
                    ldsm_x4(r0, r1, r2, r3, sb + OFF_BPL + bd);
                    bL[0][0] = r0; bL[0][1] = r1; bL[1][0] = r2; bL[1][1] = r3;
                }
#pragma unroll
                for (int mi = 0; mi < 2; mi++)
#pragma unroll
                    for (int ni = 0; ni < 2; ni++) {
                        mma_bf16(accG[mi][ni], aH[mi], bH[ni][0], bH[ni][1]);
                        mma_bf16(accG[mi][ni], aH[mi], bL[ni][0], bL[ni][1]);
                        mma_bf16(accG[mi][ni], aL[mi], bH[ni][0], bH[ni][1]);
                    }
            }
        }
#pragma unroll
        for (int mi = 0; mi < 2; mi++)
#pragma unroll
            for (int ni = 0; ni < 2; ni++)
#pragma unroll
                for (int half = 0; half < 2; half++) {
                    int t = wm * 32 + mi * 16 + quad + half * 8;
                    int s = wn * 16 + ni * 8 + qt * 2;
                    float sdt_t = s_sdt[t];
                    float v0 = accG[mi][ni][half * 2 + 0];
                    float v1 = accG[mi][ni][half * 2 + 1];
                    v0 = (t >= s)     ? v0 * expf(Ah * (sdt_t - s_sdt[s]))     : 0.f;
                    v1 = (t >= s + 1) ? v1 * expf(Ah * (sdt_t - s_sdt[s + 1])) : 0.f;
                    __nv_bfloat16 h0,l0,h1,l1;
                    hilo(v0,h0,l0); hilo(v1,h1,l1);
                    uint32_t off = swzb(t, s * 2);
                    *(__nv_bfloat162*)(smem + OFF_GH + off) = __halves2bfloat162(h0,h1);
                    *(__nv_bfloat162*)(smem + OFF_GL + off) = __halves2bfloat162(l0,l1);
                }
    }
    __syncthreads();

    // ---- GEMM4: Y = G @ U  [64t x 64p], K=s=64; U via trans-B ----
    {
        float accY[2][2][4];
#pragma unroll
        for (int mi = 0; mi < 2; mi++)
#pragma unroll
            for (int ni = 0; ni < 2; ni++)
#pragma unroll
                for (int q = 0; q < 4; q++) accY[mi][ni][q] = 0.f;

#pragma unroll
        for (int k16 = 0; k16 < 4; k16++) {
            int k2 = k16 * 2, kb = k16 * 16;
            uint32_t aH[2][4], aL[2][4], bH[2][2], bL[2][2];
#pragma unroll
            for (int mi = 0; mi < 2; mi++) {
                int row = wm * 32 + mi * 16 + a_roff;
                uint32_t ad = swz(row, k2 + a_koff);
                ldsm_x4(aH[mi][0], aH[mi][1], aH[mi][2], aH[mi][3], sb + OFF_GH + ad);
                ldsm_x4(aL[mi][0], aL[mi][1], aL[mi][2], aL[mi][3], sb + OFF_GL + ad);
            }
            {
                int row = kb + bt_row;
                int col = wn * 16 + bt_col;
                uint32_t bd = swzb(row, col * 2);
                uint32_t r0, r1, r2, r3;
                ldsm_x4_t(r0, r1, r2, r3, sb + OFF_UTH + bd);
                bH[0][0] = r0; bH[0][1] = r1; bH[1][0] = r2; bH[1][1] = r3;
                ldsm_x4_t(r0, r1, r2, r3, sb + OFF_UTL + bd);
                bL[0][0] = r0; bL[0][1] = r1; bL[1][0] = r2; bL[1][1] = r3;
            }
#pragma unroll
            for (int mi = 0; mi < 2; mi++)
#pragma unroll
                for (int ni = 0; ni < 2; ni++) {
                    mma_bf16(accY[mi][ni], aH[mi], bH[ni][0], bH[ni][1]);
                    mma_bf16(accY[mi][ni], aH[mi], bL[ni][0], bL[ni][1]);
                    mma_bf16(accY[mi][ni], aL[mi], bH[ni][0], bH[ni][1]);
                }
        }
#pragma unroll
        for (int mi = 0; mi < 2; mi++)
#pragma unroll
            for (int ni = 0; ni < 2; ni++) {
                int t = wm * 32 + mi * 16 + quad;
                int p = wn * 16 + ni * 8 + qt * 2;
                size_t o = ((size_t)b * SEQLEN + t0 + t) * DINNER + hh * HEADDIM + p;
                *(float2*)&g_y[o] = make_float2(accY[mi][ni][0], accY[mi][ni][1]);
                o += (size_t)8 * DINNER;
                *(float2*)&g_y[o] = make_float2(accY[mi][ni][2], accY[mi][ni][3]);
            }
    }

    // ---- GEMM5: Hc = Uw^T-form @ B  [64p x 128n], K=s=64 (A,B via trans) ----
    {
        float accH[2][4][4];
#pragma unroll
        for (int mi = 0; mi < 2; mi++)
#pragma unroll
            for (int ni = 0; ni < 4; ni++)
#pragma unroll
                for (int q = 0; q < 4; q++) accH[mi][ni][q] = 0.f;

#pragma unroll
        for (int k16 = 0; k16 < 4; k16++) {
            int kb = k16 * 16;
            uint32_t aH[2][4], aL[2][4], bH[4][2], bL[4][2];
#pragma unroll
            for (int mi = 0; mi < 2; mi++) {
                int row = kb + at_row;
                int col = wm * 32 + mi * 16 + at_col;
                uint32_t ad = swzb(row, col * 2);
                ldsm_x4_t(aH[mi][0], aH[mi][1], aH[mi][2], aH[mi][3], sb + OFF_UWH + ad);
                ldsm_x4_t(aL[mi][0], aL[mi][1], aL[mi][2], aL[mi][3], sb + OFF_UWL + ad);
            }
#pragma unroll
            for (int nj = 0; nj < 2; nj++) {
                int n0 = wn * 32 + nj * 16;
                int kp = n0 >> 6, ncol = n0 & 63;
                int row = kb + bt_row;
                int col = ncol + bt_col;
                uint32_t bd = kp * 8192u + swzb(row, col * 2);
                uint32_t r0, r1, r2, r3;
                ldsm_x4_t(r0, r1, r2, r3, sb + OFF_BPH + bd);
                bH[nj*2][0] = r0; bH[nj*2][1] = r1; bH[nj*2+1][0] = r2; bH[nj*2+1][1] = r3;
                ldsm_x4_t(r0, r1, r2, r3, sb + OFF_BPL + bd);
                bL[nj*2][0] = r0; bL[nj*2][1] = r1; bL[nj*2+1][0] = r2; bL[nj*2+1][1] = r3;
            }
#pragma unroll
            for (int mi = 0; mi < 2; mi++)
#pragma unroll
                for (int ni = 0; ni < 4; ni++) {
                    mma_bf16(accH[mi][ni], aH[mi], bH[ni][0], bH[ni][1]);
                    mma_bf16(accH[mi][ni], aH[mi], bL[ni][0], bL[ni][1]);
                    mma_bf16(accH[mi][ni], aL[mi], bH[ni][0], bH[ni][1]);
                }
        }
        float* hc = &g_hc[(((size_t)b * NHEADS + hh) * NCH + c) * (HEADDIM * DSTATE)];
#pragma unroll
        for (int mi = 0; mi < 2; mi++)
#pragma unroll
            for (int ni = 0; ni < 4; ni++) {
                int p = wm * 32 + mi * 16 + quad;
                int n = wn * 32 + ni * 8 + qt * 2;
                *(float2*)&hc[p * DSTATE + n] = make_float2(accH[mi][ni][0], accH[mi][ni][1]);
                *(float2*)&hc[(p + 8) * DSTATE + n] = make_float2(accH[mi][ni][2], accH[mi][ni][3]);
            }
    }
}

// =====================================================================
// SSD phase 2: inter-chunk state recurrence
// =====================================================================
__global__ __launch_bounds__(256)
void ssd_prop_kernel(const float* __restrict__ A_log)
{
    const int bh = blockIdx.x;
    const int hh = bh & (NHEADS - 1);
    const int tid = threadIdx.x;
    const float Ah = -expf(A_log[hh]);

    float4 acc[8];
#pragma unroll
    for (int j = 0; j < 8; j++) acc[j] = make_float4(0.f, 0.f, 0.f, 0.f);

    for (int c = 1; c < NCH; c++) {
        float Pi = expf(Ah * g_pi[(size_t)bh * NCH + c - 1]);
        const float4* hc = (const float4*)&g_hc[((size_t)bh * NCH + c - 1) * (HEADDIM * DSTATE)];
        float4* h0 = (float4*)&g_h0[((size_t)bh * NCH + c) * (HEADDIM * DSTATE)];
#pragma unroll
        for (int j = 0; j < 8; j++) {
            float4 v = hc[tid * 8 + j];
            acc[j].x = Pi * acc[j].x + v.x;
            acc[j].y = Pi * acc[j].y + v.y;
            acc[j].z = Pi * acc[j].z + v.z;
            acc[j].w = Pi * acc[j].w + v.w;
            h0[tid * 8 + j] = acc[j];
        }
    }
}

// =====================================================================
// SSD phase 3: carry  Y_t += r_t * (C_t @ h0)
// =====================================================================
#define C3_CPH 0u
#define C3_CPL 16384u
#define C3_H0H 32768u
#define C3_H0L 49152u
#define C3_SDT 65536u
#define C3_R   65792u
#define SMEM_SSD3 66560u

__global__ __launch_bounds__(256, 2)
void ssd_carry_kernel(const float* __restrict__ A_log)
{
    extern __shared__ __align__(1024) char smem[];
    const uint32_t sb = smem_u32(smem);
    const int c = blockIdx.x + 1, b = blockIdx.y, hh = blockIdx.z;
    const int tid = threadIdx.x;
    const int wid = tid >> 5, lane = tid & 31;
    const int wm = wid & 1, wn = wid >> 1;
    const int t0 = c * CLEN;
    const float Ah = -expf(A_log[hh]);

    float* s_sdt = (float*)(smem + C3_SDT);
    float* s_r   = (float*)(smem + C3_R);

    if (tid < 64)
        s_sdt[tid] = g_dt[((size_t)b * SEQLEN + t0 + tid) * NHEADS + hh];
    __syncthreads();
#pragma unroll
    for (int off = 1; off < 64; off <<= 1) {
        float v = 0.f;
        if (tid < 64 && tid >= off) v = s_sdt[tid - off];
        __syncthreads();
        if (tid < 64) s_sdt[tid] += v;
        __syncthreads();
    }
    if (tid < 64) s_r[tid] = expf(Ah * s_sdt[tid]);
    __syncthreads();

    const float* h0src = &g_h0[(((size_t)b * NHEADS + hh) * NCH + c) * (HEADDIM * DSTATE)];
#pragma unroll
    for (int i = 0; i < 8; i++) {
        int idx = tid + i * 256;
        int r = idx >> 5, n4 = idx & 31;
        int kp = n4 >> 4, cb = n4 & 15;
        uint32_t off = (uint32_t)kp * 8192u + (uint32_t)r * 128u
                     + ((((uint32_t)cb >> 1) ^ (r & 7)) << 4) + (cb & 1) * 8;
        {
            size_t row = ((size_t)b * SEQLEN + t0 + r) * CONVDIM;
            float4 v = *(const float4*)&g_xbc[row + DINNER + DSTATE + n4 * 4];
            __nv_bfloat16 h0b,l0,h1,l1,h2,l2,h3,l3;
            hilo(v.x,h0b,l0); hilo(v.y,h1,l1); hilo(v.z,h2,l2); hilo(v.w,h3,l3);
            *(__nv_bfloat162*)(smem + C3_CPH + off)     = __halves2bfloat162(h0b,h1);
            *(__nv_bfloat162*)(smem + C3_CPH + off + 4) = __halves2bfloat162(h2,h3);
            *(__nv_bfloat162*)(smem + C3_CPL + off)     = __halves2bfloat162(l0,l1);
            *(__nv_bfloat162*)(smem + C3_CPL + off + 4) = __halves2bfloat162(l2,l3);
        }
        {
            float4 v = *(const float4*)&h0src[r * DSTATE + n4 * 4];
            __nv_bfloat16 h0b,l0,h1,l1,h2,l2,h3,l3;
            hilo(v.x,h0b,l0); hilo(v.y,h1,l1); hilo(v.z,h2,l2); hilo(v.w,h3,l3);
            *(__nv_bfloat162*)(smem + C3_H0H + off)     = __halves2bfloat162(h0b,h1);
            *(__nv_bfloat162*)(smem + C3_H0H + off + 4) = __halves2bfloat162(h2,h3);
            *(__nv_bfloat162*)(smem + C3_H0L + off)     = __halves2bfloat162(l0,l1);
            *(__nv_bfloat162*)(smem + C3_H0L + off + 4) = __halves2bfloat162(l2,l3);
        }
    }
    __syncthreads();

    const int lgrp = lane >> 3, lr = lane & 7;
    const int a_roff = lr + (lgrp & 1) * 8;
    const int a_koff = lgrp >> 1;
    const int b_roff = lr + (lgrp >> 1) * 8;
    const int b_koff = lgrp & 1;
    const int quad = lane >> 2, qt = lane & 3;

    float acc[2][2][4];
#pragma unroll
    for (int mi = 0; mi < 2; mi++)
#pragma unroll
        for (int ni = 0; ni < 2; ni++)
#pragma unroll
            for (int q = 0; q < 4; q++) acc[mi][ni][q] = 0.f;

#pragma unroll
    for (int kp = 0; kp < 2; kp++) {
#pragma unroll
        for (int k16 = 0; k16 < 4; k16++) {
            int k2 = k16 * 2;
            uint32_t aH[2][4], aL[2][4], bH[2][2], bL[2][2];
#pragma unroll
            for (int mi = 0; mi < 2; mi++) {
                int row = wm * 32 + mi * 16 + a_roff;
                uint32_t ad = kp * 8192u + swz(row, k2 + a_koff);
                ldsm_x4(aH[mi][0], aH[mi][1], aH[mi][2], aH[mi][3], sb + C3_CPH + ad);
                ldsm_x4(aL[mi][0], aL[mi][1], aL[mi][2], aL[mi][3], sb + C3_CPL + ad);
            }
            {
                int row = wn * 16 + b_roff;
                uint32_t bd = kp * 8192u + swz(row, k2 + b_koff);
                uint32_t r0, r1, r2, r3;
                ldsm_x4(r0, r1, r2, r3, sb + C3_H0H + bd);
                bH[0][0] = r0; bH[0][1] = r1; bH[1][0] = r2; bH[1][1] = r3;
                ldsm_x4(r0, r1, r2, r3, sb + C3_H0L + bd);
                bL[0][0] = r0; bL[0][1] = r1; bL[1][0] = r2; bL[1][1] = r3;
            }
#pragma unroll
            for (int mi = 0; mi < 2; mi++)
#pragma unroll
                for (int ni = 0; ni < 2; ni++) {
                    mma_bf16(acc[mi][ni], aH[mi], bH[ni][0], bH[ni][1]);
                    mma_bf16(acc[mi][ni], aH[mi], bL[ni][0], bL[ni][1]);
                    mma_bf16(acc[mi][ni], aL[mi], bH[ni][0], bH[ni][1]);
                }
        }
    }

#pragma unroll
    for (int mi = 0; mi < 2; mi++)
#pragma unroll
        for (int ni = 0; ni < 2; ni++) {
            int t = wm * 32 + mi * 16 + quad;
            int p = wn * 16 + ni * 8 + qt * 2;
            {
                float rt = s_r[t];
                size_t o = ((size_t)b * SEQLEN + t0 + t) * DINNER + hh * HEADDIM + p;
                float2 v = *(float2*)&g_y[o];
                v.x += rt * acc[mi][ni][0];
                v.y += rt * acc[mi][ni][1];
                *(float2*)&g_y[o] = v;
            }
            {
                float rt = s_r[t + 8];
                size_t o = ((size_t)b * SEQLEN + t0 + t + 8) * DINNER + hh * HEADDIM + p;
                float2 v = *(float2*)&g_y[o];
                v.x += rt * acc[mi][ni][2];
                v.y += rt * acc[mi][ni][3];
                *(float2*)&g_y[o] = v;
            }
        }
}

// =====================================================================
// skip + gate + RMSNorm -> bf16 hi/lo
// =====================================================================
__global__ __launch_bounds__(256)
void gate_norm_kernel(const float* __restrict__ Dw, const float* __restrict__ norm_w)
{
    const int t = blockIdx.x;
    const int b = blockIdx.y;
    const size_t row = (size_t)b * SEQLEN + t;
    const float4* __restrict__ z4 = (const float4*)&g_zx [row * DINPROJ];
    const float4* __restrict__ x4 = (const float4*)&g_xbc[row * CONVDIM];
    const float4* __restrict__ y4 = (const float4*)&g_y  [row * DINNER];

    float4 vals[2];
    float ss = 0.f;
#pragma unroll
    for (int r = 0; r < 2; r++) {
        int f = r * 256 + threadIdx.x;
        float dv = Dw[f >> 4];
        float4 a = y4[f], xv = x4[f], zv = z4[f];
        float4 v;
        v.x = a.x + dv * xv.x;
        v.y = a.y + dv * xv.y;
        v.z = a.z + dv * xv.z;
        v.w = a.w + dv * xv.w;
        v.x *= zv.x / (1.f + expf(-zv.x));
        v.y *= zv.y / (1.f + expf(-zv.y));
        v.z *= zv.z / (1.f + expf(-zv.z));
        v.w *= zv.w / (1.f + expf(-zv.w));
        vals[r] = v;
        ss += v.x * v.x + v.y * v.y + v.z * v.z + v.w * v.w;
    }
    __shared__ float red[256];
    red[threadIdx.x] = ss;
    __syncthreads();
    for (int off = 128; off > 0; off >>= 1) {
        if (threadIdx.x < off) red[threadIdx.x] += red[threadIdx.x + off];
        __syncthreads();
    }
    float scale = rsqrtf(red[0] / (float)DINNER + EPS);
    __nv_bfloat162* outh = (__nv_bfloat162*)&g_ynh[row * DINNER];
    __nv_bfloat162* outl = (__nv_bfloat162*)&g_ynl[row * DINNER];
    const float4* nw4 = (const float4*)norm_w;
#pragma unroll
    for (int r = 0; r < 2; r++) {
        int f = r * 256 + threadIdx.x;
        float4 w = nw4[f];
        float4 v = vals[r];
        v.x *= scale * w.x; v.y *= scale * w.y; v.z *= scale * w.z; v.w *= scale * w.w;
        split4(v, outh, outl, f);
    }
}

// =====================================================================
extern "C" void kernel_launch(void* const* d_in, const int* in_sizes, int n_in,
                              void* d_out, int out_size)
{
    const float* x          = (const float*)d_in[0];
    const float* in_proj_w  = (const float*)d_in[1];
    const float* conv_w     = (const float*)d_in[2];
    const float* conv_b     = (const float*)d_in[3];
    const float* dt_bias    = (const float*)d_in[4];
    const float* A_log      = (const float*)d_in[5];
    const float* Dw         = (const float*)d_in[6];
    const float* norm_w     = (const float*)d_in[7];
    const float* out_proj_w = (const float*)d_in[8];
    float* out = (float*)d_out;

    float *p_zx = nullptr;
    void *p_xh, *p_xl, *p_w1h, *p_w1l, *p_w2h, *p_w2l, *p_ynh, *p_ynl;
    cudaGetSymbolAddress((void**)&p_zx, g_zx);
    cudaGetSymbolAddress(&p_xh,  g_xh);  cudaGetSymbolAddress(&p_xl,  g_xl);
    cudaGetSymbolAddress(&p_w1h, g_w1h); cudaGetSymbolAddress(&p_w1l, g_w1l);
    cudaGetSymbolAddress(&p_w2h, g_w2h); cudaGetSymbolAddress(&p_w2l, g_w2l);
    cudaGetSymbolAddress(&p_ynh, g_ynh); cudaGetSymbolAddress(&p_ynl, g_ynl);

    cudaFuncSetAttribute(gemm_mma<false>, cudaFuncAttributeMaxDynamicSharedMemorySize, SMEM_GEMM);
    cudaFuncSetAttribute(gemm_mma<true>,  cudaFuncAttributeMaxDynamicSharedMemorySize, SMEM_GEMM);
    cudaFuncSetAttribute(ssd_chunk_kernel, cudaFuncAttributeMaxDynamicSharedMemorySize, SMEM_SSD1);
    cudaFuncSetAttribute(ssd_carry_kernel, cudaFuncAttributeMaxDynamicSharedMemorySize, SMEM_SSD3);

    // 0) fp32 -> bf16 hi/lo conversions
    {
        int total4 = N4_X + N4_W1 + N4_W2;
        cvt_all<<<(total4 + 255)/256, 256>>>(
            (const float4*)x, (const float4*)in_proj_w, (const float4*)out_proj_w);
    }

    // 1) zxbcdt = x @ in_proj_w^T
    gemm_mma<false><<<dim3((DINPROJ + BN - 1)/BN, ROWS/BM), 256, SMEM_GEMM>>>(
        (const __nv_bfloat16*)p_xh, (const __nv_bfloat16*)p_xl,
        (const __nv_bfloat16*)p_w1h, (const __nv_bfloat16*)p_w1l,
        nullptr, p_zx, DINPROJ, DMODEL);

    // 2) conv + SiLU; dt softplus
    conv_act_kernel<<<dim3(CONVDIM/256, SEQLEN/4, BATCH), 256>>>(conv_w, conv_b, dt_bias);

    // 3) SSD scan
    ssd_chunk_kernel<<<dim3(NCH, BATCH, NHEADS), 256, SMEM_SSD1>>>(A_log);
    ssd_prop_kernel<<<BATCH * NHEADS, 256>>>(A_log);
    ssd_carry_kernel<<<dim3(NCH - 1, BATCH, NHEADS), 256, SMEM_SSD3>>>(A_log);

    // 4) skip + gate + RMSNorm
    gate_norm_kernel<<<dim3(SEQLEN, BATCH), 256>>>(Dw, norm_w);

    // 5) out = x + yn @ out_proj_w^T
    gemm_mma<true><<<dim3(DMODEL/BN, ROWS/BM), 256, SMEM_GEMM>>>(
        (const __nv_bfloat16*)p_ynh, (const __nv_bfloat16*)p_ynl,
        (const __nv_bfloat16*)p_w2h, (const __nv_bfloat16*)p_w2l,
        x, out, DMODEL, DINNER);
}